// round 5
// baseline (speedup 1.0000x reference)
#include <cuda_runtime.h>
#include <math.h>
#include <stdint.h>

#define BSZ 8
#define SEQ 1024
#define DIM 1024
#define NH 16
#define HD 64
#define MTOT 8192
#define DCAT 1088
#define DFF 2048

// Scratch (__device__ globals per allocation-free rule)
__device__ float g_qkv[(size_t)MTOT * 3072];   // q | k | v   [m, 3072]
__device__ float g_cat[(size_t)MTOT * DCAT];
__device__ float g_h[(size_t)MTOT * DFF];

__device__ __forceinline__ unsigned fu(float x) { return __float_as_uint(x); }
__device__ __forceinline__ float to_tf32(float x) {
    unsigned u; asm("cvt.rna.tf32.f32 %0, %1;" : "=r"(u) : "f"(x));
    return __uint_as_float(u);
}
__device__ __forceinline__ unsigned to_tf32_u(float x) {
    unsigned u; asm("cvt.rna.tf32.f32 %0, %1;" : "=r"(u) : "f"(x));
    return u;
}
__device__ __forceinline__ float4 to_tf32_4(float4 v) {
    v.x = to_tf32(v.x); v.y = to_tf32(v.y); v.z = to_tf32(v.z); v.w = to_tf32(v.w);
    return v;
}
__device__ __forceinline__ void mma_frag(float c[4], const unsigned a[4], const unsigned b[2]) {
    asm volatile(
        "mma.sync.aligned.m16n8k8.row.col.f32.tf32.tf32.f32 "
        "{%0,%1,%2,%3}, {%4,%5,%6,%7}, {%8,%9}, {%0,%1,%2,%3};"
        : "+f"(c[0]), "+f"(c[1]), "+f"(c[2]), "+f"(c[3])
        : "r"(a[0]), "r"(a[1]), "r"(a[2]), "r"(a[3]), "r"(b[0]), "r"(b[1]));
}
__device__ __forceinline__ uint32_t smem_u32(const void* p) {
    uint32_t a;
    asm("{ .reg .u64 t; cvta.to.shared.u64 t, %1; cvt.u32.u64 %0, t; }" : "=r"(a) : "l"(p));
    return a;
}
__device__ __forceinline__ void cp_async16(uint32_t dst, const void* src) {
    asm volatile("cp.async.cg.shared.global [%0], [%1], 16;" :: "r"(dst), "l"(src));
}
#define CP_COMMIT() asm volatile("cp.async.commit_group;" ::: "memory")
#define CP_WAIT0()  asm volatile("cp.async.wait_group 0;" ::: "memory")

// ---------------------------------------------------------------------------
// tf32 mma GEMM v2.1. CTA 128x128, BK=32, 256 thr = 8 warps (2M x 4N), warp 64x32.
// A smem: k-permuted (k,k+4 adjacent), cvt.rna applied at STS time.
// B smem: raw fp32 via cp.async (double buffer); cvt.rna at fragment load.
// ---------------------------------------------------------------------------
#define ASTR 40
#define BSTR 136
#define A_WORDS (128 * ASTR)            // 5120
#define B_WORDS (32 * BSTR)             // 4352
#define STAGE_WORDS (A_WORDS + B_WORDS) // 9472
#define SMEM_BYTES (2 * STAGE_WORDS * 4)  // 75776

__device__ __forceinline__ void gemm_core2(
    const float* __restrict__ A, int K, int m0,
    const float* __restrict__ B, int ldB, int n0B, int sh /*log2(ncols/4)*/,
    const float* __restrict__ bias, float* __restrict__ C, int ldC, int c0,
    int relu, float* sm)
{
    const int tid = threadIdx.x, lane = tid & 31, warp = tid >> 5;
    const int wm = warp & 1, wn = warp >> 1;
    const int g = lane >> 2, tg = lane & 3;
    const int ncols = 4 << sh;
    const uint32_t ss = smem_u32(sm);

    const int aoff[2] = {0, STAGE_WORDS};
    const int boff[2] = {A_WORDS, STAGE_WORDS + A_WORDS};

    float acc[4][4][4];
#pragma unroll
    for (int mi = 0; mi < 4; mi++)
#pragma unroll
        for (int ni = 0; ni < 4; ni++)
#pragma unroll
            for (int r = 0; r < 4; r++) acc[mi][ni][r] = 0.f;

    const int NC = K >> 5;
    const int nb_iters = (8 * ncols) >> 8;   // float4s per thread for B chunk
    float4 areg[4];

    // --- prologue: chunk 0 ---
#pragma unroll
    for (int i = 0; i < 4; i++) {
        int idx = i * 256 + tid;
        int r = idx >> 3, kq = (idx & 7) << 2;
        areg[i] = *(const float4*)(A + (size_t)(m0 + r) * K + kq);
    }
    for (int i = 0; i < nb_iters; i++) {
        int idx = i * 256 + tid;
        int row = idx >> sh, n4 = (idx & ((1 << sh) - 1)) << 2;
        cp_async16(ss + (boff[0] + row * BSTR + n4) * 4,
                   B + (size_t)row * ldB + n0B + n4);
    }
    CP_COMMIT();
#pragma unroll
    for (int i = 0; i < 4; i++) {
        int idx = i * 256 + tid;
        int r = idx >> 3, kq = (idx & 7) << 2;
        int w = aoff[0] + r * ASTR + ((kq & 4) >> 2) + (kq & 24);
        float4 v = to_tf32_4(areg[i]);
        sm[w + 0] = v.x; sm[w + 2] = v.y;
        sm[w + 4] = v.z; sm[w + 6] = v.w;
    }
    CP_WAIT0();
    __syncthreads();

    for (int ch = 0; ch < NC; ch++) {
        const int s = ch & 1;
        const bool more = (ch + 1 < NC);
        if (more) {
            const int k0 = (ch + 1) << 5;
#pragma unroll
            for (int i = 0; i < 4; i++) {
                int idx = i * 256 + tid;
                int r = idx >> 3, kq = (idx & 7) << 2;
                areg[i] = *(const float4*)(A + (size_t)(m0 + r) * K + k0 + kq);
            }
            for (int i = 0; i < nb_iters; i++) {
                int idx = i * 256 + tid;
                int row = idx >> sh, n4 = (idx & ((1 << sh) - 1)) << 2;
                cp_async16(ss + (boff[s ^ 1] + row * BSTR + n4) * 4,
                           B + (size_t)(k0 + row) * ldB + n0B + n4);
            }
            CP_COMMIT();
        }

        // ---- compute on stage s ----
        const float* As = sm + aoff[s];
        const float* Bs = sm + boff[s];
#pragma unroll
        for (int ks = 0; ks < 4; ks++) {
            unsigned a[4][4];
#pragma unroll
            for (int mi = 0; mi < 4; mi++) {
                const float* ap = As + (wm * 64 + mi * 16 + g) * ASTR + ks * 8 + tg * 2;
                float2 lo = *(const float2*)(ap);
                float2 hi = *(const float2*)(ap + 8 * ASTR);
                a[mi][0] = fu(lo.x); a[mi][1] = fu(hi.x);
                a[mi][2] = fu(lo.y); a[mi][3] = fu(hi.y);
            }
#pragma unroll
            for (int ni = 0; ni < 4; ni++) {
                const float* bp = Bs + (ks * 8 + tg) * BSTR + wn * 32 + ni * 8 + g;
                unsigned bb[2] = { to_tf32_u(bp[0]), to_tf32_u(bp[4 * BSTR]) };
#pragma unroll
                for (int mi = 0; mi < 4; mi++)
                    mma_frag(acc[mi][ni], a[mi], bb);
            }
        }

        if (more) {
#pragma unroll
            for (int i = 0; i < 4; i++) {
                int idx = i * 256 + tid;
                int r = idx >> 3, kq = (idx & 7) << 2;
                int w = aoff[s ^ 1] + r * ASTR + ((kq & 4) >> 2) + (kq & 24);
                float4 v = to_tf32_4(areg[i]);
                sm[w + 0] = v.x; sm[w + 2] = v.y;
                sm[w + 4] = v.z; sm[w + 6] = v.w;
            }
            CP_WAIT0();
        }
        __syncthreads();
    }

    // ---- epilogue ----
    if (wn * 32 >= ncols) return;
#pragma unroll
    for (int mi = 0; mi < 4; mi++) {
        int r = m0 + wm * 64 + mi * 16 + g;
#pragma unroll
        for (int ni = 0; ni < 4; ni++) {
            int cl = wn * 32 + ni * 8 + 2 * tg;      // ncols-local column
            float b0 = bias[cl], b1 = bias[cl + 1];
            float v0 = acc[mi][ni][0] + b0, v1 = acc[mi][ni][1] + b1;
            float v2 = acc[mi][ni][2] + b0, v3 = acc[mi][ni][3] + b1;
            if (relu) {
                v0 = fmaxf(v0, 0.f); v1 = fmaxf(v1, 0.f);
                v2 = fmaxf(v2, 0.f); v3 = fmaxf(v3, 0.f);
            }
            *(float2*)(C + (size_t)r * ldC + c0 + cl)       = make_float2(v0, v1);
            *(float2*)(C + (size_t)(r + 8) * ldC + c0 + cl) = make_float2(v2, v3);
        }
    }
}

__global__ __launch_bounds__(256) void gemm_v2(
    const float* __restrict__ A, int K,
    const float* __restrict__ B, int ldB,
    const float* __restrict__ bias, float* __restrict__ C, int ldC, int relu)
{
    extern __shared__ float sm[];
    const int n0 = blockIdx.x * 128;
    gemm_core2(A, K, blockIdx.y * 128, B, ldB, n0, 5, bias + n0, C, ldC, n0, relu, sm);
}

__global__ __launch_bounds__(256) void qkv_v2(
    const float* __restrict__ x,
    const float* __restrict__ Wq, const float* __restrict__ bq,
    const float* __restrict__ Wk, const float* __restrict__ bk,
    const float* __restrict__ Wv, const float* __restrict__ bv,
    const float* __restrict__ Wi, const float* __restrict__ bi)
{
    extern __shared__ float sm[];
    const int nt = blockIdx.x;     // 0..23 -> q/k/v tiles, 24 -> in-proj
    if (nt < 24) {
        const int seg = nt >> 3, tile = nt & 7;
        const float* W  = (seg == 0) ? Wq : (seg == 1) ? Wk : Wv;
        const float* bb = (seg == 0) ? bq : (seg == 1) ? bk : bv;
        gemm_core2(x, 1024, blockIdx.y * 128, W, 1024, tile * 128, 5,
                   bb + tile * 128, g_qkv, 3072, seg * 1024 + tile * 128, 0, sm);
    } else {
        gemm_core2(x, 1024, blockIdx.y * 128, Wi, 64, 0, 4,
                   bi, g_cat + DIM, DCAT, 0, 0, sm);
    }
}

// ---------------------------------------------------------------------------
// Flash attention (legacy tf32 mma), reads g_qkv [m,3072], writes g_cat[:,0:1024].
// ---------------------------------------------------------------------------
#define QSTR 68
#define KSTR 68
#define VSTR 72
#define PSTR 36

__global__ __launch_bounds__(128) void attn_mma()
{
    __shared__ float Qs[64 * QSTR];
    __shared__ float Ks[32 * KSTR];
    __shared__ float Vs[32 * VSTR];
    __shared__ float Ps[4 * 16 * PSTR];

    const int tid = threadIdx.x, lane = tid & 31, warp = tid >> 5;
    const int g = lane >> 2, tg = lane & 3;
    const int b = blockIdx.z, h = blockIdx.y, q0 = blockIdx.x * 64;
    const float* base = g_qkv + (size_t)(b * SEQ) * 3072 + h * HD;

    {
#pragma unroll
        for (int i = 0; i < 8; i++) {
            int idx = i * 128 + tid;
            int r = idx >> 4, c4 = (idx & 15) * 4;
            float4 v = *(const float4*)(base + (size_t)(q0 + r) * 3072 + c4);
            v.x *= 0.125f; v.y *= 0.125f; v.z *= 0.125f; v.w *= 0.125f;
            *(float4*)(Qs + r * QSTR + c4) = to_tf32_4(v);
        }
    }

    float rowm[2] = {-1e30f, -1e30f};
    float rowl[2] = {0.f, 0.f};
    float o[8][4];
#pragma unroll
    for (int nf = 0; nf < 8; nf++)
#pragma unroll
        for (int r = 0; r < 4; r++) o[nf][r] = 0.f;

    const int qrow0 = q0 + warp * 16 + g;
    float* Pw = Ps + warp * 16 * PSTR;
    const float* kbase = base + 1024;
    const float* vbase = base + 2048;

    for (int c0 = 0; c0 < SEQ; c0 += 32) {
        __syncthreads();
#pragma unroll
        for (int i = 0; i < 4; i++) {
            int idx = i * 128 + tid;
            int r = idx >> 4, c4 = (idx & 15) * 4;
            float4 kv = *(const float4*)(kbase + (size_t)(c0 + r) * 3072 + c4);
            *(float4*)(Ks + r * KSTR + c4) = to_tf32_4(kv);
            float4 vv = *(const float4*)(vbase + (size_t)(c0 + r) * 3072 + c4);
            *(float4*)(Vs + r * VSTR + c4) = to_tf32_4(vv);
        }
        __syncthreads();

        float s[4][4];
#pragma unroll
        for (int ni = 0; ni < 4; ni++)
#pragma unroll
            for (int r = 0; r < 4; r++) s[ni][r] = 0.f;
#pragma unroll
        for (int ks = 0; ks < 8; ks++) {
            const int kc = ks * 8;
            unsigned a[4];
            const float* qp = Qs + (warp * 16 + g) * QSTR + kc + tg;
            a[0] = fu(qp[0]);       a[1] = fu(qp[8 * QSTR]);
            a[2] = fu(qp[4]);       a[3] = fu(qp[8 * QSTR + 4]);
#pragma unroll
            for (int ni = 0; ni < 4; ni++) {
                const float* kp = Ks + (ni * 8 + g) * KSTR + kc + tg;
                unsigned bb[2] = { fu(kp[0]), fu(kp[4]) };
                mma_frag(s[ni], a, bb);
            }
        }

        float cm0 = -1e30f, cm1 = -1e30f;
#pragma unroll
        for (int ni = 0; ni < 4; ni++) {
            int col = c0 + ni * 8 + 2 * tg;
            if (col     == qrow0)     s[ni][0] = -1e30f;
            if (col + 1 == qrow0)     s[ni][1] = -1e30f;
            if (col     == qrow0 + 8) s[ni][2] = -1e30f;
            if (col + 1 == qrow0 + 8) s[ni][3] = -1e30f;
            cm0 = fmaxf(cm0, fmaxf(s[ni][0], s[ni][1]));
            cm1 = fmaxf(cm1, fmaxf(s[ni][2], s[ni][3]));
        }
        cm0 = fmaxf(cm0, __shfl_xor_sync(0xffffffffu, cm0, 1));
        cm0 = fmaxf(cm0, __shfl_xor_sync(0xffffffffu, cm0, 2));
        cm1 = fmaxf(cm1, __shfl_xor_sync(0xffffffffu, cm1, 1));
        cm1 = fmaxf(cm1, __shfl_xor_sync(0xffffffffu, cm1, 2));

        float mn0 = fmaxf(rowm[0], cm0), mn1 = fmaxf(rowm[1], cm1);
        float sc0 = __expf(rowm[0] - mn0), sc1 = __expf(rowm[1] - mn1);
        rowm[0] = mn0; rowm[1] = mn1;
        rowl[0] *= sc0; rowl[1] *= sc1;
#pragma unroll
        for (int nf = 0; nf < 8; nf++) {
            o[nf][0] *= sc0; o[nf][1] *= sc0;
            o[nf][2] *= sc1; o[nf][3] *= sc1;
        }

        float ls0 = 0.f, ls1 = 0.f;
#pragma unroll
        for (int ni = 0; ni < 4; ni++) {
            float p0 = __expf(s[ni][0] - mn0), p1 = __expf(s[ni][1] - mn0);
            float p2 = __expf(s[ni][2] - mn1), p3 = __expf(s[ni][3] - mn1);
            ls0 += p0 + p1; ls1 += p2 + p3;
            float* pp = Pw + g * PSTR + ni * 8 + 2 * tg;
            pp[0] = to_tf32(p0);            pp[1] = to_tf32(p1);
            pp[8 * PSTR] = to_tf32(p2);     pp[8 * PSTR + 1] = to_tf32(p3);
        }
        ls0 += __shfl_xor_sync(0xffffffffu, ls0, 1);
        ls0 += __shfl_xor_sync(0xffffffffu, ls0, 2);
        ls1 += __shfl_xor_sync(0xffffffffu, ls1, 1);
        ls1 += __shfl_xor_sync(0xffffffffu, ls1, 2);
        rowl[0] += ls0; rowl[1] += ls1;
        __syncwarp();

#pragma unroll
        for (int ks = 0; ks < 4; ks++) {
            const int kc = ks * 8;
            unsigned a[4];
            const float* pp = Pw + g * PSTR + kc + tg;
            a[0] = fu(pp[0]);       a[1] = fu(pp[8 * PSTR]);
            a[2] = fu(pp[4]);       a[3] = fu(pp[8 * PSTR + 4]);
#pragma unroll
            for (int nf = 0; nf < 8; nf++) {
                const float* vp = Vs + (kc + tg) * VSTR + nf * 8 + g;
                unsigned bb[2] = { fu(vp[0]), fu(vp[4 * VSTR]) };
                mma_frag(o[nf], a, bb);
            }
        }
    }

    float inv0 = 1.f / rowl[0], inv1 = 1.f / rowl[1];
    float* orow = g_cat + (size_t)(b * SEQ + qrow0) * DCAT + h * HD;
#pragma unroll
    for (int nf = 0; nf < 8; nf++) {
        int c = nf * 8 + 2 * tg;
        *(float2*)(orow + c)            = make_float2(o[nf][0] * inv0, o[nf][1] * inv0);
        *(float2*)(orow + 8 * DCAT + c) = make_float2(o[nf][2] * inv1, o[nf][3] * inv1);
    }
}

// ---------------------------------------------------------------------------
extern "C" void kernel_launch(void* const* d_in, const int* in_sizes, int n_in,
                              void* d_out, int out_size)
{
    const float* x   = (const float*)d_in[0];
    const float* Wq  = (const float*)d_in[1];
    const float* bq  = (const float*)d_in[2];
    const float* Wk  = (const float*)d_in[3];
    const float* bk  = (const float*)d_in[4];
    const float* Wv  = (const float*)d_in[5];
    const float* bv  = (const float*)d_in[6];
    const float* Wi  = (const float*)d_in[7];
    const float* bi  = (const float*)d_in[8];
    const float* W1  = (const float*)d_in[9];
    const float* b1  = (const float*)d_in[10];
    const float* W2  = (const float*)d_in[11];
    const float* b2  = (const float*)d_in[12];
    float* out = (float*)d_out;

    float *catp = nullptr, *hp = nullptr;
    cudaGetSymbolAddress((void**)&catp, g_cat);
    cudaGetSymbolAddress((void**)&hp, g_h);

    static bool configured = false;
    if (!configured) {
        cudaFuncSetAttribute(qkv_v2,  cudaFuncAttributeMaxDynamicSharedMemorySize, SMEM_BYTES);
        cudaFuncSetAttribute(gemm_v2, cudaFuncAttributeMaxDynamicSharedMemorySize, SMEM_BYTES);
        configured = true;
    }

    // QKV + input projection: 24 x 128-col tiles + 1 x 64-col tile; 64 m-tiles
    qkv_v2<<<dim3(25, 64), 256, SMEM_BYTES>>>(x, Wq, bq, Wk, bk, Wv, bv, Wi, bi);
    // Attention -> g_cat[:, 0:1024]
    attn_mma<<<dim3(SEQ / 64, NH, BSZ), 128>>>();
    // FFN1: [8192,1088] @ [1088,2048] + b1, relu -> g_h
    gemm_v2<<<dim3(DFF / 128, MTOT / 128), 256, SMEM_BYTES>>>(catp, DCAT, W1, DFF, b1, hp, DFF, 1);
    // FFN2: [8192,2048] @ [2048,1024] + b2 -> out
    gemm_v2<<<dim3(DIM / 128, MTOT / 128), 256, SMEM_BYTES>>>(hp, DFF, W2, DIM, b2, out, DIM, 0);
}

// round 7
// speedup vs baseline: 1.7186x; 1.7186x over previous
#include <cuda_runtime.h>
#include <cuda_fp16.h>
#include <math.h>
#include <stdint.h>

#define BSZ 8
#define SEQ 1024
#define DIM 1024
#define NH 16
#define HD 64
#define MTOT 8192
#define DCAT 1088
#define DFF 2048

// Scratch (__device__ globals per allocation-free rule)
__device__ float g_qkv[(size_t)MTOT * 3072];   // q | k | v   [m, 3072]
__device__ float g_cat[(size_t)MTOT * DCAT];
__device__ float g_h[(size_t)MTOT * DFF];

// Pre-converted weights: packed k-pairs, word(kp, n) = half2(W[2kp][n], W[2kp+1][n])
__device__ __half2 g_whq[512 * 1024];
__device__ __half2 g_whk[512 * 1024];
__device__ __half2 g_whv[512 * 1024];
__device__ __half2 g_whi[512 * 64];
__device__ __half2 g_wh1[544 * 2048];
__device__ __half2 g_wh2[1024 * 1024];

__device__ __forceinline__ unsigned fu(float x) { return __float_as_uint(x); }
__device__ __forceinline__ unsigned h2u(__half2 h) { return *(unsigned*)&h; }
__device__ __forceinline__ float to_tf32(float x) {
    unsigned u; asm("cvt.rna.tf32.f32 %0, %1;" : "=r"(u) : "f"(x));
    return __uint_as_float(u);
}
__device__ __forceinline__ float4 to_tf32_4(float4 v) {
    v.x = to_tf32(v.x); v.y = to_tf32(v.y); v.z = to_tf32(v.z); v.w = to_tf32(v.w);
    return v;
}
__device__ __forceinline__ void mma_f16(float c[4], const unsigned a[4],
                                        unsigned b0, unsigned b1) {
    asm volatile(
        "mma.sync.aligned.m16n8k16.row.col.f32.f16.f16.f32 "
        "{%0,%1,%2,%3}, {%4,%5,%6,%7}, {%8,%9}, {%0,%1,%2,%3};"
        : "+f"(c[0]), "+f"(c[1]), "+f"(c[2]), "+f"(c[3])
        : "r"(a[0]), "r"(a[1]), "r"(a[2]), "r"(a[3]), "r"(b0), "r"(b1));
}
__device__ __forceinline__ void mma_frag(float c[4], const unsigned a[4], const unsigned b[2]) {
    asm volatile(
        "mma.sync.aligned.m16n8k8.row.col.f32.tf32.tf32.f32 "
        "{%0,%1,%2,%3}, {%4,%5,%6,%7}, {%8,%9}, {%0,%1,%2,%3};"
        : "+f"(c[0]), "+f"(c[1]), "+f"(c[2]), "+f"(c[3])
        : "r"(a[0]), "r"(a[1]), "r"(a[2]), "r"(a[3]), "r"(b[0]), "r"(b[1]));
}
__device__ __forceinline__ uint32_t smem_u32(const void* p) {
    uint32_t a;
    asm("{ .reg .u64 t; cvta.to.shared.u64 t, %1; cvt.u32.u64 %0, t; }" : "=r"(a) : "l"(p));
    return a;
}
__device__ __forceinline__ void cp_async16(uint32_t dst, const void* src) {
    asm volatile("cp.async.cg.shared.global [%0], [%1], 16;" :: "r"(dst), "l"(src));
}
#define CP_COMMIT() asm volatile("cp.async.commit_group;" ::: "memory")
#define CP_WAIT0()  asm volatile("cp.async.wait_group 0;" ::: "memory")

// ---------------------------------------------------------------------------
// Weight conversion: W [2*kp_total, N] fp32 -> Wh [kp_total, N] half2 (k-pairs)
// ---------------------------------------------------------------------------
__global__ __launch_bounds__(256) void conv_w(
    const float* __restrict__ W, __half2* __restrict__ Wh, int kp_total, int N)
{
    int idx = blockIdx.x * 256 + threadIdx.x;
    int nq = N >> 2;
    if (idx >= kp_total * nq) return;
    int kp = idx / nq, n4 = (idx - kp * nq) << 2;
    float4 a = *(const float4*)(W + (size_t)(2 * kp) * N + n4);
    float4 b = *(const float4*)(W + (size_t)(2 * kp + 1) * N + n4);
    uint4 o;
    o.x = h2u(__floats2half2_rn(a.x, b.x));
    o.y = h2u(__floats2half2_rn(a.y, b.y));
    o.z = h2u(__floats2half2_rn(a.z, b.z));
    o.w = h2u(__floats2half2_rn(a.w, b.w));
    *(uint4*)(Wh + (size_t)kp * N + n4) = o;
}

// ---------------------------------------------------------------------------
// fp16 mma GEMM v3.1. CTA 128x128, BK=32, 256 thr = 8 warps (2M x 4N), warp 64x32.
// A: fp32 gmem -> cvt at STS, permuted half2 rows (LDS.64 frags), stride 24 words.
// B: pre-packed half2 [kp][N] gmem -> raw cp.async, rows of 136 words.
// Double-buffered, 2 CTAs/SM.
// ---------------------------------------------------------------------------
#define ASTR3 24
#define BSTR3 136
#define A3_WORDS (128 * ASTR3)           // 3072
#define B3_WORDS (16 * BSTR3)            // 2176
#define STG3 (A3_WORDS + B3_WORDS)       // 5248 words
#define SMEM3 (2 * STG3 * 4)             // 41984 B

__device__ __forceinline__ void a_sts(unsigned* Aw, int base_off, int idx, float4 v) {
    int r = idx >> 3, kq = (idx & 7) << 2;
    int j0 = kq >> 1;                         // even h2 index 0..14
    int p0 = ((j0 & 3) << 1) | ((j0 & 4) >> 2);
    int w = base_off + r * ASTR3 + (j0 & 8) + p0;
    Aw[w]     = h2u(__floats2half2_rn(v.x, v.y));
    Aw[w + 2] = h2u(__floats2half2_rn(v.z, v.w));
}

__device__ __forceinline__ void gemm_core3(
    const float* __restrict__ A, int K, int m0,
    const __half2* __restrict__ Bh, int ldw, int n0w, int ncols,
    const float* __restrict__ bias, float* __restrict__ C, int ldC, int c0,
    int relu, float* sm)
{
    const int tid = threadIdx.x, lane = tid & 31, warp = tid >> 5;
    const int wm = warp & 1, wn = warp >> 1;
    const int g = lane >> 2, tg = lane & 3;
    const uint32_t ss = smem_u32(sm);
    unsigned* smw = (unsigned*)sm;

    const int aoff[2] = {0, STG3};
    const int boff[2] = {A3_WORDS, STG3 + A3_WORDS};

    float acc[4][4][4];
#pragma unroll
    for (int mi = 0; mi < 4; mi++)
#pragma unroll
        for (int ni = 0; ni < 4; ni++)
#pragma unroll
            for (int r = 0; r < 4; r++) acc[mi][ni][r] = 0.f;

    const int NC = K >> 5;
    const int gpr = ncols >> 2;      // 16B granules per B row (4 half2 words each)
    const int ngr = 16 * gpr;        // granules per 16-row chunk
    float4 areg[4];

    // --- prologue: chunk 0 ---
#pragma unroll
    for (int i = 0; i < 4; i++) {
        int idx = i * 256 + tid;
        areg[i] = *(const float4*)(A + (size_t)(m0 + (idx >> 3)) * K + ((idx & 7) << 2));
    }
    for (int gi = tid; gi < ngr; gi += 256) {
        int row = gi / gpr, n4 = (gi - row * gpr) << 2;
        cp_async16(ss + (boff[0] + row * BSTR3 + n4) * 4,
                   Bh + (size_t)row * ldw + n0w + n4);
    }
    CP_COMMIT();
#pragma unroll
    for (int i = 0; i < 4; i++)
        a_sts(smw, aoff[0], i * 256 + tid, areg[i]);
    CP_WAIT0();
    __syncthreads();

    for (int ch = 0; ch < NC; ch++) {
        const int s = ch & 1;
        const bool more = (ch + 1 < NC);
        if (more) {
            const int k0 = (ch + 1) << 5;
#pragma unroll
            for (int i = 0; i < 4; i++) {
                int idx = i * 256 + tid;
                areg[i] = *(const float4*)(A + (size_t)(m0 + (idx >> 3)) * K + k0 + ((idx & 7) << 2));
            }
            const int kp0 = (ch + 1) << 4;
            for (int gi = tid; gi < ngr; gi += 256) {
                int row = gi / gpr, n4 = (gi - row * gpr) << 2;
                cp_async16(ss + (boff[s ^ 1] + row * BSTR3 + n4) * 4,
                           Bh + (size_t)(kp0 + row) * ldw + n0w + n4);
            }
            CP_COMMIT();
        }

        // ---- compute on stage s ----
        const unsigned* Aw = smw + aoff[s];
        const unsigned* Bw = smw + boff[s];
#pragma unroll
        for (int ks = 0; ks < 2; ks++) {
            unsigned a[4][4];
#pragma unroll
            for (int mi = 0; mi < 4; mi++) {
                int row = wm * 64 + mi * 16 + g;
                uint2 lo = *(const uint2*)(Aw + row * ASTR3 + ks * 8 + 2 * tg);
                uint2 hi = *(const uint2*)(Aw + (row + 8) * ASTR3 + ks * 8 + 2 * tg);
                a[mi][0] = lo.x; a[mi][1] = hi.x;
                a[mi][2] = lo.y; a[mi][3] = hi.y;
            }
#pragma unroll
            for (int ni = 0; ni < 4; ni++) {
                int colw = wn * 32 + ni * 8 + g;
                unsigned b0 = Bw[(ks * 8 + tg) * BSTR3 + colw];
                unsigned b1 = Bw[(ks * 8 + tg + 4) * BSTR3 + colw];
#pragma unroll
                for (int mi = 0; mi < 4; mi++)
                    mma_f16(acc[mi][ni], a[mi], b0, b1);
            }
        }

        if (more) {
#pragma unroll
            for (int i = 0; i < 4; i++)
                a_sts(smw, aoff[s ^ 1], i * 256 + tid, areg[i]);
            CP_WAIT0();
        }
        __syncthreads();
    }

    // ---- epilogue ----
    if (wn * 32 >= ncols) return;
#pragma unroll
    for (int mi = 0; mi < 4; mi++) {
        int r = m0 + wm * 64 + mi * 16 + g;
#pragma unroll
        for (int ni = 0; ni < 4; ni++) {
            int cl = wn * 32 + ni * 8 + 2 * tg;
            float b0 = bias[cl], b1 = bias[cl + 1];
            float v0 = acc[mi][ni][0] + b0, v1 = acc[mi][ni][1] + b1;
            float v2 = acc[mi][ni][2] + b0, v3 = acc[mi][ni][3] + b1;
            if (relu) {
                v0 = fmaxf(v0, 0.f); v1 = fmaxf(v1, 0.f);
                v2 = fmaxf(v2, 0.f); v3 = fmaxf(v3, 0.f);
            }
            *(float2*)(C + (size_t)r * ldC + c0 + cl)       = make_float2(v0, v1);
            *(float2*)(C + (size_t)(r + 8) * ldC + c0 + cl) = make_float2(v2, v3);
        }
    }
}

__global__ __launch_bounds__(256, 2) void gemm_v3(
    const float* __restrict__ A, int K,
    const __half2* __restrict__ Bh, int ldw,
    const float* __restrict__ bias, float* __restrict__ C, int ldC, int relu)
{
    extern __shared__ float sm[];
    const int n0 = blockIdx.x * 128;
    gemm_core3(A, K, blockIdx.y * 128, Bh, ldw, n0, 128, bias + n0, C, ldC, n0, relu, sm);
}

__global__ __launch_bounds__(256, 2) void qkv_v3(
    const float* __restrict__ x,
    const float* __restrict__ bq, const float* __restrict__ bk,
    const float* __restrict__ bv, const float* __restrict__ bi)
{
    extern __shared__ float sm[];
    const int nt = blockIdx.x;     // 0..23 -> q/k/v tiles, 24 -> in-proj
    if (nt < 24) {
        const int seg = nt >> 3, tile = nt & 7;
        const __half2* W = (seg == 0) ? g_whq : (seg == 1) ? g_whk : g_whv;
        const float* bb  = (seg == 0) ? bq : (seg == 1) ? bk : bv;
        gemm_core3(x, 1024, blockIdx.y * 128, W, 1024, tile * 128, 128,
                   bb + tile * 128, g_qkv, 3072, seg * 1024 + tile * 128, 0, sm);
    } else {
        gemm_core3(x, 1024, blockIdx.y * 128, g_whi, 64, 0, 64,
                   bi, g_cat + DIM, DCAT, 0, 0, sm);
    }
}

// ---------------------------------------------------------------------------
// Flash attention (legacy tf32 mma), reads g_qkv [m,3072], writes g_cat[:,0:1024].
// ---------------------------------------------------------------------------
#define QSTR 68
#define KSTR 68
#define VSTR 72
#define PSTR 36

__global__ __launch_bounds__(128) void attn_mma()
{
    __shared__ float Qs[64 * QSTR];
    __shared__ float Ks[32 * KSTR];
    __shared__ float Vs[32 * VSTR];
    __shared__ float Ps[4 * 16 * PSTR];

    const int tid = threadIdx.x, lane = tid & 31, warp = tid >> 5;
    const int g = lane >> 2, tg = lane & 3;
    const int b = blockIdx.z, h = blockIdx.y, q0 = blockIdx.x * 64;
    const float* base = g_qkv + (size_t)(b * SEQ) * 3072 + h * HD;

    {
#pragma unroll
        for (int i = 0; i < 8; i++) {
            int idx = i * 128 + tid;
            int r = idx >> 4, c4 = (idx & 15) * 4;
            float4 v = *(const float4*)(base + (size_t)(q0 + r) * 3072 + c4);
            v.x *= 0.125f; v.y *= 0.125f; v.z *= 0.125f; v.w *= 0.125f;
            *(float4*)(Qs + r * QSTR + c4) = to_tf32_4(v);
        }
    }

    float rowm[2] = {-1e30f, -1e30f};
    float rowl[2] = {0.f, 0.f};
    float o[8][4];
#pragma unroll
    for (int nf = 0; nf < 8; nf++)
#pragma unroll
        for (int r = 0; r < 4; r++) o[nf][r] = 0.f;

    const int qrow0 = q0 + warp * 16 + g;
    float* Pw = Ps + warp * 16 * PSTR;
    const float* kbase = base + 1024;
    const float* vbase = base + 2048;

    for (int c0 = 0; c0 < SEQ; c0 += 32) {
        __syncthreads();
#pragma unroll
        for (int i = 0; i < 4; i++) {
            int idx = i * 128 + tid;
            int r = idx >> 4, c4 = (idx & 15) * 4;
            float4 kv = *(const float4*)(kbase + (size_t)(c0 + r) * 3072 + c4);
            *(float4*)(Ks + r * KSTR + c4) = to_tf32_4(kv);
            float4 vv = *(const float4*)(vbase + (size_t)(c0 + r) * 3072 + c4);
            *(float4*)(Vs + r * VSTR + c4) = to_tf32_4(vv);
        }
        __syncthreads();

        float s[4][4];
#pragma unroll
        for (int ni = 0; ni < 4; ni++)
#pragma unroll
            for (int r = 0; r < 4; r++) s[ni][r] = 0.f;
#pragma unroll
        for (int ks = 0; ks < 8; ks++) {
            const int kc = ks * 8;
            unsigned a[4];
            const float* qp = Qs + (warp * 16 + g) * QSTR + kc + tg;
            a[0] = fu(qp[0]);       a[1] = fu(qp[8 * QSTR]);
            a[2] = fu(qp[4]);       a[3] = fu(qp[8 * QSTR + 4]);
#pragma unroll
            for (int ni = 0; ni < 4; ni++) {
                const float* kp = Ks + (ni * 8 + g) * KSTR + kc + tg;
                unsigned bb[2] = { fu(kp[0]), fu(kp[4]) };
                mma_frag(s[ni], a, bb);
            }
        }

        float cm0 = -1e30f, cm1 = -1e30f;
#pragma unroll
        for (int ni = 0; ni < 4; ni++) {
            int col = c0 + ni * 8 + 2 * tg;
            if (col     == qrow0)     s[ni][0] = -1e30f;
            if (col + 1 == qrow0)     s[ni][1] = -1e30f;
            if (col     == qrow0 + 8) s[ni][2] = -1e30f;
            if (col + 1 == qrow0 + 8) s[ni][3] = -1e30f;
            cm0 = fmaxf(cm0, fmaxf(s[ni][0], s[ni][1]));
            cm1 = fmaxf(cm1, fmaxf(s[ni][2], s[ni][3]));
        }
        cm0 = fmaxf(cm0, __shfl_xor_sync(0xffffffffu, cm0, 1));
        cm0 = fmaxf(cm0, __shfl_xor_sync(0xffffffffu, cm0, 2));
        cm1 = fmaxf(cm1, __shfl_xor_sync(0xffffffffu, cm1, 1));
        cm1 = fmaxf(cm1, __shfl_xor_sync(0xffffffffu, cm1, 2));

        float mn0 = fmaxf(rowm[0], cm0), mn1 = fmaxf(rowm[1], cm1);
        float sc0 = __expf(rowm[0] - mn0), sc1 = __expf(rowm[1] - mn1);
        rowm[0] = mn0; rowm[1] = mn1;
        rowl[0] *= sc0; rowl[1] *= sc1;
#pragma unroll
        for (int nf = 0; nf < 8; nf++) {
            o[nf][0] *= sc0; o[nf][1] *= sc0;
            o[nf][2] *= sc1; o[nf][3] *= sc1;
        }

        float ls0 = 0.f, ls1 = 0.f;
#pragma unroll
        for (int ni = 0; ni < 4; ni++) {
            float p0 = __expf(s[ni][0] - mn0), p1 = __expf(s[ni][1] - mn0);
            float p2 = __expf(s[ni][2] - mn1), p3 = __expf(s[ni][3] - mn1);
            ls0 += p0 + p1; ls1 += p2 + p3;
            float* pp = Pw + g * PSTR + ni * 8 + 2 * tg;
            pp[0] = to_tf32(p0);            pp[1] = to_tf32(p1);
            pp[8 * PSTR] = to_tf32(p2);     pp[8 * PSTR + 1] = to_tf32(p3);
        }
        ls0 += __shfl_xor_sync(0xffffffffu, ls0, 1);
        ls0 += __shfl_xor_sync(0xffffffffu, ls0, 2);
        ls1 += __shfl_xor_sync(0xffffffffu, ls1, 1);
        ls1 += __shfl_xor_sync(0xffffffffu, ls1, 2);
        rowl[0] += ls0; rowl[1] += ls1;
        __syncwarp();

#pragma unroll
        for (int ks = 0; ks < 4; ks++) {
            const int kc = ks * 8;
            unsigned a[4];
            const float* pp = Pw + g * PSTR + kc + tg;
            a[0] = fu(pp[0]);       a[1] = fu(pp[8 * PSTR]);
            a[2] = fu(pp[4]);       a[3] = fu(pp[8 * PSTR + 4]);
#pragma unroll
            for (int nf = 0; nf < 8; nf++) {
                const float* vp = Vs + (kc + tg) * VSTR + nf * 8 + g;
                unsigned bb[2] = { fu(vp[0]), fu(vp[4 * VSTR]) };
                mma_frag(o[nf], a, bb);
            }
        }
    }

    float inv0 = 1.f / rowl[0], inv1 = 1.f / rowl[1];
    float* orow = g_cat + (size_t)(b * SEQ + qrow0) * DCAT + h * HD;
#pragma unroll
    for (int nf = 0; nf < 8; nf++) {
        int c = nf * 8 + 2 * tg;
        *(float2*)(orow + c)            = make_float2(o[nf][0] * inv0, o[nf][1] * inv0);
        *(float2*)(orow + 8 * DCAT + c) = make_float2(o[nf][2] * inv1, o[nf][3] * inv1);
    }
}

// ---------------------------------------------------------------------------
extern "C" void kernel_launch(void* const* d_in, const int* in_sizes, int n_in,
                              void* d_out, int out_size)
{
    const float* x   = (const float*)d_in[0];
    const float* Wq  = (const float*)d_in[1];
    const float* bq  = (const float*)d_in[2];
    const float* Wk  = (const float*)d_in[3];
    const float* bk  = (const float*)d_in[4];
    const float* Wv  = (const float*)d_in[5];
    const float* bv  = (const float*)d_in[6];
    const float* Wi  = (const float*)d_in[7];
    const float* bi  = (const float*)d_in[8];
    const float* W1  = (const float*)d_in[9];
    const float* b1  = (const float*)d_in[10];
    const float* W2  = (const float*)d_in[11];
    const float* b2  = (const float*)d_in[12];
    float* out = (float*)d_out;

    float *catp = nullptr, *hp = nullptr;
    __half2 *whq, *whk, *whv, *whi, *wh1, *wh2;
    cudaGetSymbolAddress((void**)&catp, g_cat);
    cudaGetSymbolAddress((void**)&hp, g_h);
    cudaGetSymbolAddress((void**)&whq, g_whq);
    cudaGetSymbolAddress((void**)&whk, g_whk);
    cudaGetSymbolAddress((void**)&whv, g_whv);
    cudaGetSymbolAddress((void**)&whi, g_whi);
    cudaGetSymbolAddress((void**)&wh1, g_wh1);
    cudaGetSymbolAddress((void**)&wh2, g_wh2);

    // Weight pre-conversion (few µs total)
    conv_w<<<(512 * 256 + 255) / 256, 256>>>(Wq, whq, 512, 1024);
    conv_w<<<(512 * 256 + 255) / 256, 256>>>(Wk, whk, 512, 1024);
    conv_w<<<(512 * 256 + 255) / 256, 256>>>(Wv, whv, 512, 1024);
    conv_w<<<(512 * 16 + 255) / 256, 256>>>(Wi, whi, 512, 64);
    conv_w<<<(544 * 512 + 255) / 256, 256>>>(W1, wh1, 544, 2048);
    conv_w<<<(1024 * 256 + 255) / 256, 256>>>(W2, wh2, 1024, 1024);

    // QKV + input projection: 24 x 128-col tiles + 1 x 64-col tile; 64 m-tiles
    qkv_v3<<<dim3(25, 64), 256, SMEM3>>>(x, bq, bk, bv, bi);
    // Attention -> g_cat[:, 0:1024]
    attn_mma<<<dim3(SEQ / 64, NH, BSZ), 128>>>();
    // FFN1: [8192,1088] @ [1088,2048] + b1, relu -> g_h
    gemm_v3<<<dim3(DFF / 128, MTOT / 128), 256, SMEM3>>>(catp, DCAT, wh1, DFF, b1, hp, DFF, 1);
    // FFN2: [8192,2048] @ [2048,1024] + b2 -> out
    gemm_v3<<<dim3(DIM / 128, MTOT / 128), 256, SMEM3>>>(hp, DFF, wh2, DIM, b2, out, DIM, 0);
}

// round 9
// speedup vs baseline: 2.1394x; 1.2449x over previous
#include <cuda_runtime.h>
#include <cuda_fp16.h>
#include <math.h>
#include <stdint.h>

#define BSZ 8
#define SEQ 1024
#define DIM 1024
#define NH 16
#define HD 64
#define MTOT 8192
#define DCAT 1088
#define DFF 2048

// fp16 intermediates (__device__ globals per allocation-free rule), half2 words
__device__ __half2 g_xh[(size_t)MTOT * 512];      // x            [m, 512w]
__device__ __half2 g_qkvh[(size_t)MTOT * 1536];   // q|k|v        [m, 1536w]
__device__ __half2 g_cath[(size_t)MTOT * 544];    // attn|inproj  [m, 544w]
__device__ __half2 g_hh[(size_t)MTOT * 1024];     // ffn hidden   [m, 1024w]

// Pre-converted weights: word(kp, n) = half2(W[2kp][n], W[2kp+1][n])
__device__ __half2 g_whq[512 * 1024];
__device__ __half2 g_whk[512 * 1024];
__device__ __half2 g_whv[512 * 1024];
__device__ __half2 g_whi[512 * 64];
__device__ __half2 g_wh1[544 * 2048];
__device__ __half2 g_wh2[1024 * 1024];

__device__ __forceinline__ unsigned h2u(__half2 h) { return *(unsigned*)&h; }
__device__ __forceinline__ __half2 u2h(unsigned u) { return *(__half2*)&u; }
__device__ __forceinline__ void mma_f16(float c[4], const unsigned a[4],
                                        unsigned b0, unsigned b1) {
    asm volatile(
        "mma.sync.aligned.m16n8k16.row.col.f32.f16.f16.f32 "
        "{%0,%1,%2,%3}, {%4,%5,%6,%7}, {%8,%9}, {%0,%1,%2,%3};"
        : "+f"(c[0]), "+f"(c[1]), "+f"(c[2]), "+f"(c[3])
        : "r"(a[0]), "r"(a[1]), "r"(a[2]), "r"(a[3]), "r"(b0), "r"(b1));
}
__device__ __forceinline__ uint32_t smem_u32(const void* p) {
    uint32_t a;
    asm("{ .reg .u64 t; cvta.to.shared.u64 t, %1; cvt.u32.u64 %0, t; }" : "=r"(a) : "l"(p));
    return a;
}
__device__ __forceinline__ void cp_async16(uint32_t dst, const void* src) {
    asm volatile("cp.async.cg.shared.global [%0], [%1], 16;" :: "r"(dst), "l"(src));
}
#define CP_COMMIT() asm volatile("cp.async.commit_group;" ::: "memory")
#define CP_WAIT0()  asm volatile("cp.async.wait_group 0;" ::: "memory")

// ---------------------------------------------------------------------------
// Conversions
// ---------------------------------------------------------------------------
__global__ __launch_bounds__(256) void conv_w(
    const float* __restrict__ W, __half2* __restrict__ Wh, int kp_total, int N)
{
    int idx = blockIdx.x * 256 + threadIdx.x;
    int nq = N >> 2;
    if (idx >= kp_total * nq) return;
    int kp = idx / nq, n4 = (idx - kp * nq) << 2;
    float4 a = *(const float4*)(W + (size_t)(2 * kp) * N + n4);
    float4 b = *(const float4*)(W + (size_t)(2 * kp + 1) * N + n4);
    uint4 o;
    o.x = h2u(__floats2half2_rn(a.x, b.x));
    o.y = h2u(__floats2half2_rn(a.y, b.y));
    o.z = h2u(__floats2half2_rn(a.z, b.z));
    o.w = h2u(__floats2half2_rn(a.w, b.w));
    *(uint4*)(Wh + (size_t)kp * N + n4) = o;
}

// x fp32 [m, 1024] -> g_xh [m, 512w] (natural k-pairs along row)
__global__ __launch_bounds__(256) void conv_x(const float* __restrict__ x)
{
    int idx = blockIdx.x * 256 + threadIdx.x;
    int row = idx >> 8, c4 = (idx & 255) << 2;
    float4 v = *(const float4*)(x + (size_t)row * DIM + c4);
    uint2 o;
    o.x = h2u(__floats2half2_rn(v.x, v.y));
    o.y = h2u(__floats2half2_rn(v.z, v.w));
    *(uint2*)((unsigned*)g_xh + (size_t)row * 512 + (c4 >> 1)) = o;
}

// ---------------------------------------------------------------------------
// fp16 GEMM v4: all-half. CTA 128x128, BK=32, 256 thr = 8 warps (2M x 4N).
// A: half gmem rows -> raw cp.async, smem rows 16 data words pad to 20.
// B: packed half2 [kp][N] -> raw cp.async, rows of 136 words. Double buffered.
// ---------------------------------------------------------------------------
#define ASTR4 20
#define BSTR4 136
#define A4W (128 * ASTR4)     // 2560
#define B4W (16 * BSTR4)      // 2176
#define STG4 (A4W + B4W)      // 4736 words
#define SMEM4 (2 * STG4 * 4)  // 37888 B

template<bool OUTH, bool RELU>
__device__ __forceinline__ void gemm_core4(
    const __half2* __restrict__ Ah, int ldaw, int K, int m0,
    const __half2* __restrict__ Bh, int ldw, int n0w, int ncols,
    const float* __restrict__ bias, void* Cp, int ldCo, int c0o,
    unsigned* smw)
{
    const int tid = threadIdx.x, lane = tid & 31, warp = tid >> 5;
    const int wm = warp & 1, wn = warp >> 1;
    const int g = lane >> 2, tg = lane & 3;
    const uint32_t ss = smem_u32(smw);

    const int aoff[2] = {0, STG4};
    const int boff[2] = {A4W, STG4 + A4W};

    float acc[4][4][4];
#pragma unroll
    for (int mi = 0; mi < 4; mi++)
#pragma unroll
        for (int ni = 0; ni < 4; ni++)
#pragma unroll
            for (int r = 0; r < 4; r++) acc[mi][ni][r] = 0.f;

    const int NC = K >> 5;
    const int gpr = ncols >> 2;
    const int ngr = 16 * gpr;

    // --- prologue: chunk 0 ---
#pragma unroll
    for (int i = 0; i < 2; i++) {
        int gi = i * 256 + tid;
        int row = gi >> 2, c4 = (gi & 3) << 2;
        cp_async16(ss + (aoff[0] + row * ASTR4 + c4) * 4,
                   Ah + (size_t)(m0 + row) * ldaw + c4);
    }
    for (int gi = tid; gi < ngr; gi += 256) {
        int row = gi / gpr, n4 = (gi - row * gpr) << 2;
        cp_async16(ss + (boff[0] + row * BSTR4 + n4) * 4,
                   Bh + (size_t)row * ldw + n0w + n4);
    }
    CP_COMMIT();
    CP_WAIT0();
    __syncthreads();

    for (int ch = 0; ch < NC; ch++) {
        const int s = ch & 1;
        const bool more = (ch + 1 < NC);
        if (more) {
            const int k0w = (ch + 1) << 4;
#pragma unroll
            for (int i = 0; i < 2; i++) {
                int gi = i * 256 + tid;
                int row = gi >> 2, c4 = (gi & 3) << 2;
                cp_async16(ss + (aoff[s ^ 1] + row * ASTR4 + c4) * 4,
                           Ah + (size_t)(m0 + row) * ldaw + k0w + c4);
            }
            for (int gi = tid; gi < ngr; gi += 256) {
                int row = gi / gpr, n4 = (gi - row * gpr) << 2;
                cp_async16(ss + (boff[s ^ 1] + row * BSTR4 + n4) * 4,
                           Bh + (size_t)(k0w + row) * ldw + n0w + n4);
            }
            CP_COMMIT();
        }

        const unsigned* Aw = smw + aoff[s];
        const unsigned* Bw = smw + boff[s];
#pragma unroll
        for (int ks = 0; ks < 2; ks++) {
            unsigned a[4][4];
#pragma unroll
            for (int mi = 0; mi < 4; mi++) {
                const unsigned* ap = Aw + (wm * 64 + mi * 16 + g) * ASTR4 + ks * 8 + tg;
                a[mi][0] = ap[0];             a[mi][2] = ap[4];
                a[mi][1] = ap[8 * ASTR4];     a[mi][3] = ap[8 * ASTR4 + 4];
            }
#pragma unroll
            for (int ni = 0; ni < 4; ni++) {
                const unsigned* bp = Bw + (ks * 8 + tg) * BSTR4 + wn * 32 + ni * 8 + g;
                unsigned b0 = bp[0], b1 = bp[4 * BSTR4];
#pragma unroll
                for (int mi = 0; mi < 4; mi++)
                    mma_f16(acc[mi][ni], a[mi], b0, b1);
            }
        }

        if (more) CP_WAIT0();
        __syncthreads();
    }

    // ---- epilogue ----
    if (wn * 32 >= ncols) return;
#pragma unroll
    for (int mi = 0; mi < 4; mi++) {
        int r = m0 + wm * 64 + mi * 16 + g;
#pragma unroll
        for (int ni = 0; ni < 4; ni++) {
            int cl = wn * 32 + ni * 8 + 2 * tg;
            float b0 = bias[cl], b1 = bias[cl + 1];
            float v0 = acc[mi][ni][0] + b0, v1 = acc[mi][ni][1] + b1;
            float v2 = acc[mi][ni][2] + b0, v3 = acc[mi][ni][3] + b1;
            if (RELU) {
                v0 = fmaxf(v0, 0.f); v1 = fmaxf(v1, 0.f);
                v2 = fmaxf(v2, 0.f); v3 = fmaxf(v3, 0.f);
            }
            if (OUTH) {
                unsigned* Ch = (unsigned*)Cp;
                int w = c0o + wn * 16 + ni * 4 + tg;
                Ch[(size_t)r * ldCo + w]       = h2u(__floats2half2_rn(v0, v1));
                Ch[(size_t)(r + 8) * ldCo + w] = h2u(__floats2half2_rn(v2, v3));
            } else {
                float* Cf = (float*)Cp;
                *(float2*)(Cf + (size_t)r * ldCo + c0o + cl)       = make_float2(v0, v1);
                *(float2*)(Cf + (size_t)(r + 8) * ldCo + c0o + cl) = make_float2(v2, v3);
            }
        }
    }
}

__global__ __launch_bounds__(256, 2) void qkv_v4(
    const float* __restrict__ bq, const float* __restrict__ bk,
    const float* __restrict__ bv, const float* __restrict__ bi)
{
    extern __shared__ unsigned smw[];
    const int nt = blockIdx.x, m0 = blockIdx.y * 128;
    if (nt < 24) {
        const int seg = nt >> 3, tile = nt & 7;
        const __half2* W = (seg == 0) ? g_whq : (seg == 1) ? g_whk : g_whv;
        const float* bb  = (seg == 0) ? bq : (seg == 1) ? bk : bv;
        gemm_core4<true, false>(g_xh, 512, 1024, m0, W, 1024, tile * 128, 128,
                                bb + tile * 128, g_qkvh, 1536,
                                seg * 512 + tile * 64, smw);
    } else {
        gemm_core4<true, false>(g_xh, 512, 1024, m0, g_whi, 64, 0, 64,
                                bi, g_cath, 544, 512, smw);
    }
}

__global__ __launch_bounds__(256, 2) void ffn1_v4(const float* __restrict__ b1)
{
    extern __shared__ unsigned smw[];
    const int n0 = blockIdx.x * 128;
    gemm_core4<true, true>(g_cath, 544, 1088, blockIdx.y * 128, g_wh1, DFF, n0, 128,
                           b1 + n0, g_hh, 1024, n0 >> 1, smw);
}

__global__ __launch_bounds__(256, 2) void ffn2_v4(const float* __restrict__ b2,
                                                  float* __restrict__ out)
{
    extern __shared__ unsigned smw[];
    const int n0 = blockIdx.x * 128;
    gemm_core4<false, false>(g_hh, 1024, 2048, blockIdx.y * 128, g_wh2, DIM, n0, 128,
                             b2 + n0, out, DIM, n0, smw);
}

// ---------------------------------------------------------------------------
// fp16 flash attention. CTA 128 thr / 4 warps, 64 q rows, 32-key chunks.
// HD=64 -> 32 half2 words per row.
// ---------------------------------------------------------------------------
#define AQSTR 36
#define AVSTR 20
#define APSTR 20

__global__ __launch_bounds__(128) void attn_f16()
{
    __shared__ unsigned Qs[64 * AQSTR];
    __shared__ unsigned Ks[32 * AQSTR];
    __shared__ unsigned Vt[64 * AVSTR];
    __shared__ unsigned Ps[4 * 16 * APSTR];

    const int tid = threadIdx.x, lane = tid & 31, warp = tid >> 5;
    const int g = lane >> 2, tg = lane & 3;
    const int b = blockIdx.z, h = blockIdx.y, q0 = blockIdx.x * 64;

    const unsigned* qbase = (const unsigned*)g_qkvh + (size_t)(b * SEQ) * 1536 + h * 32;
    const unsigned* kbase = qbase + 512;
    const unsigned* vbase = qbase + 1024;

    // Q tile 64 rows x 32 words, scaled by 0.125 (512 uint4 / 128 thr = 4)
    {
        const __half2 qsc = __float2half2_rn(0.125f);
#pragma unroll
        for (int i = 0; i < 4; i++) {
            int idx = i * 128 + tid;
            int row = idx >> 3, c4 = (idx & 7) << 2;
            uint4 v = *(const uint4*)(qbase + (size_t)(q0 + row) * 1536 + c4);
            __half2* hp = (__half2*)&v;
            hp[0] = __hmul2(hp[0], qsc); hp[1] = __hmul2(hp[1], qsc);
            hp[2] = __hmul2(hp[2], qsc); hp[3] = __hmul2(hp[3], qsc);
            *(uint4*)(Qs + row * AQSTR + c4) = v;
        }
    }

    float rowm[2] = {-1e30f, -1e30f};
    float rowl[2] = {0.f, 0.f};
    float o[8][4];
#pragma unroll
    for (int nf = 0; nf < 8; nf++)
#pragma unroll
        for (int r = 0; r < 4; r++) o[nf][r] = 0.f;

    const int qrow0 = q0 + warp * 16 + g;
    unsigned* Pw = Ps + warp * 16 * APSTR;

    for (int c0 = 0; c0 < SEQ; c0 += 32) {
        __syncthreads();
        // K tile 32 rows x 32 words (256 uint4 / 128 thr = 2)
#pragma unroll
        for (int i = 0; i < 2; i++) {
            int idx = i * 128 + tid;
            int row = idx >> 3, c4 = (idx & 7) << 2;
            *(uint4*)(Ks + row * AQSTR + c4) =
                *(const uint4*)(kbase + (size_t)(c0 + row) * 1536 + c4);
        }
        // V transpose to Vt[d][kp]: d rows 0..63 (wi = word 0..31), kp 0..15
        {
            int wi = tid & 31, rb = tid >> 5;
#pragma unroll
            for (int rr = rb; rr < 16; rr += 4) {
                unsigned u0 = vbase[(size_t)(c0 + 2 * rr) * 1536 + wi];
                unsigned u1 = vbase[(size_t)(c0 + 2 * rr + 1) * 1536 + wi];
                __half2 va = u2h(u0), vb = u2h(u1);
                Vt[(2 * wi) * AVSTR + rr]     = h2u(__lows2half2(va, vb));
                Vt[(2 * wi + 1) * AVSTR + rr] = h2u(__highs2half2(va, vb));
            }
        }
        __syncthreads();

        // S (16x32 per warp) = Q · K^T, d=64 -> 4 ksteps
        float s[4][4];
#pragma unroll
        for (int ni = 0; ni < 4; ni++)
#pragma unroll
            for (int r = 0; r < 4; r++) s[ni][r] = 0.f;
#pragma unroll
        for (int ks = 0; ks < 4; ks++) {
            unsigned a[4];
            const unsigned* qp = Qs + (warp * 16 + g) * AQSTR + ks * 8 + tg;
            a[0] = qp[0];             a[2] = qp[4];
            a[1] = qp[8 * AQSTR];     a[3] = qp[8 * AQSTR + 4];
#pragma unroll
            for (int ni = 0; ni < 4; ni++) {
                const unsigned* kp = Ks + (ni * 8 + g) * AQSTR + ks * 8 + tg;
                mma_f16(s[ni], a, kp[0], kp[4]);
            }
        }

        // Diagonal mask + online softmax
        float cm0 = -1e30f, cm1 = -1e30f;
#pragma unroll
        for (int ni = 0; ni < 4; ni++) {
            int col = c0 + ni * 8 + 2 * tg;
            if (col     == qrow0)     s[ni][0] = -1e30f;
            if (col + 1 == qrow0)     s[ni][1] = -1e30f;
            if (col     == qrow0 + 8) s[ni][2] = -1e30f;
            if (col + 1 == qrow0 + 8) s[ni][3] = -1e30f;
            cm0 = fmaxf(cm0, fmaxf(s[ni][0], s[ni][1]));
            cm1 = fmaxf(cm1, fmaxf(s[ni][2], s[ni][3]));
        }
        cm0 = fmaxf(cm0, __shfl_xor_sync(0xffffffffu, cm0, 1));
        cm0 = fmaxf(cm0, __shfl_xor_sync(0xffffffffu, cm0, 2));
        cm1 = fmaxf(cm1, __shfl_xor_sync(0xffffffffu, cm1, 1));
        cm1 = fmaxf(cm1, __shfl_xor_sync(0xffffffffu, cm1, 2));

        float mn0 = fmaxf(rowm[0], cm0), mn1 = fmaxf(rowm[1], cm1);
        float sc0 = __expf(rowm[0] - mn0), sc1 = __expf(rowm[1] - mn1);
        rowm[0] = mn0; rowm[1] = mn1;
        rowl[0] *= sc0; rowl[1] *= sc1;
#pragma unroll
        for (int nf = 0; nf < 8; nf++) {
            o[nf][0] *= sc0; o[nf][1] *= sc0;
            o[nf][2] *= sc1; o[nf][3] *= sc1;
        }

        float ls0 = 0.f, ls1 = 0.f;
#pragma unroll
        for (int ni = 0; ni < 4; ni++) {
            float p0 = __expf(s[ni][0] - mn0), p1 = __expf(s[ni][1] - mn0);
            float p2 = __expf(s[ni][2] - mn1), p3 = __expf(s[ni][3] - mn1);
            ls0 += p0 + p1; ls1 += p2 + p3;
            Pw[g * APSTR + ni * 4 + tg]       = h2u(__floats2half2_rn(p0, p1));
            Pw[(g + 8) * APSTR + ni * 4 + tg] = h2u(__floats2half2_rn(p2, p3));
        }
        ls0 += __shfl_xor_sync(0xffffffffu, ls0, 1);
        ls0 += __shfl_xor_sync(0xffffffffu, ls0, 2);
        ls1 += __shfl_xor_sync(0xffffffffu, ls1, 1);
        ls1 += __shfl_xor_sync(0xffffffffu, ls1, 2);
        rowl[0] += ls0; rowl[1] += ls1;
        __syncwarp();

        // O += P(16x32) · V(32x64): 2 ksteps of 16 keys
#pragma unroll
        for (int ks = 0; ks < 2; ks++) {
            unsigned a[4];
            a[0] = Pw[g * APSTR + ks * 8 + tg];
            a[1] = Pw[(g + 8) * APSTR + ks * 8 + tg];
            a[2] = Pw[g * APSTR + ks * 8 + tg + 4];
            a[3] = Pw[(g + 8) * APSTR + ks * 8 + tg + 4];
#pragma unroll
            for (int nf = 0; nf < 8; nf++) {
                const unsigned* vp = Vt + (nf * 8 + g) * AVSTR + ks * 8 + tg;
                mma_f16(o[nf], a, vp[0], vp[4]);
            }
        }
    }

    // Epilogue: normalize, store half2 into g_cath[:, h*32w .. +32w]
    float inv0 = 1.f / rowl[0], inv1 = 1.f / rowl[1];
    unsigned* orow = (unsigned*)g_cath + (size_t)(b * SEQ + qrow0) * 544 + h * 32;
#pragma unroll
    for (int nf = 0; nf < 8; nf++) {
        int w = nf * 4 + tg;
        orow[w]           = h2u(__floats2half2_rn(o[nf][0] * inv0, o[nf][1] * inv0));
        orow[8 * 544 + w] = h2u(__floats2half2_rn(o[nf][2] * inv1, o[nf][3] * inv1));
    }
}

// ---------------------------------------------------------------------------
extern "C" void kernel_launch(void* const* d_in, const int* in_sizes, int n_in,
                              void* d_out, int out_size)
{
    const float* x   = (const float*)d_in[0];
    const float* Wq  = (const float*)d_in[1];
    const float* bq  = (const float*)d_in[2];
    const float* Wk  = (const float*)d_in[3];
    const float* bk  = (const float*)d_in[4];
    const float* Wv  = (const float*)d_in[5];
    const float* bv  = (const float*)d_in[6];
    const float* Wi  = (const float*)d_in[7];
    const float* bi  = (const float*)d_in[8];
    const float* W1  = (const float*)d_in[9];
    const float* b1  = (const float*)d_in[10];
    const float* W2  = (const float*)d_in[11];
    const float* b2  = (const float*)d_in[12];
    float* out = (float*)d_out;

    __half2 *whq, *whk, *whv, *whi, *wh1, *wh2;
    cudaGetSymbolAddress((void**)&whq, g_whq);
    cudaGetSymbolAddress((void**)&whk, g_whk);
    cudaGetSymbolAddress((void**)&whv, g_whv);
    cudaGetSymbolAddress((void**)&whi, g_whi);
    cudaGetSymbolAddress((void**)&wh1, g_wh1);
    cudaGetSymbolAddress((void**)&wh2, g_wh2);

    static bool configured = false;
    if (!configured) {
        cudaFuncSetAttribute(qkv_v4,  cudaFuncAttributeMaxDynamicSharedMemorySize, SMEM4);
        cudaFuncSetAttribute(ffn1_v4, cudaFuncAttributeMaxDynamicSharedMemorySize, SMEM4);
        cudaFuncSetAttribute(ffn2_v4, cudaFuncAttributeMaxDynamicSharedMemorySize, SMEM4);
        configured = true;
    }

    // Conversions
    conv_x<<<MTOT, 256>>>(x);
    conv_w<<<(512 * 256 + 255) / 256, 256>>>(Wq, whq, 512, 1024);
    conv_w<<<(512 * 256 + 255) / 256, 256>>>(Wk, whk, 512, 1024);
    conv_w<<<(512 * 256 + 255) / 256, 256>>>(Wv, whv, 512, 1024);
    conv_w<<<(512 * 16 + 255) / 256, 256>>>(Wi, whi, 512, 64);
    conv_w<<<(544 * 512 + 255) / 256, 256>>>(W1, wh1, 544, 2048);
    conv_w<<<(1024 * 256 + 255) / 256, 256>>>(W2, wh2, 1024, 1024);

    // QKV + input projection
    qkv_v4<<<dim3(25, 64), 256, SMEM4>>>(bq, bk, bv, bi);
    // Attention -> g_cath[:, 0:512w]
    attn_f16<<<dim3(SEQ / 64, NH, BSZ), 128>>>();
    // FFN1 -> g_hh (relu)
    ffn1_v4<<<dim3(DFF / 128, MTOT / 128), 256, SMEM4>>>(b1);
    // FFN2 -> out (fp32)
    ffn2_v4<<<dim3(DIM / 128, MTOT / 128), 256, SMEM4>>>(b2, out);
}

// round 10
// speedup vs baseline: 2.3044x; 1.0771x over previous
#include <cuda_runtime.h>
#include <cuda_fp16.h>
#include <math.h>
#include <stdint.h>

#define BSZ 8
#define SEQ 1024
#define DIM 1024
#define NH 16
#define HD 64
#define MTOT 8192
#define DCAT 1088
#define DFF 2048

// fp16 intermediates (__device__ globals per allocation-free rule), half2 words
__device__ __half2 g_xh[(size_t)MTOT * 512];      // x            [m, 512w]
__device__ __half2 g_qkvh[(size_t)MTOT * 1536];   // q|k|v        [m, 1536w]
__device__ __half2 g_cath[(size_t)MTOT * 544];    // attn|inproj  [m, 544w]
__device__ __half2 g_hh[(size_t)MTOT * 1024];     // ffn hidden   [m, 1024w]

// Pre-converted weights: word(kp, n) = half2(W[2kp][n], W[2kp+1][n])
__device__ __half2 g_whq[512 * 1024];
__device__ __half2 g_whk[512 * 1024];
__device__ __half2 g_whv[512 * 1024];
__device__ __half2 g_whi[512 * 64];
__device__ __half2 g_wh1[544 * 2048];
__device__ __half2 g_wh2[1024 * 1024];

__device__ __forceinline__ unsigned h2u(__half2 h) { return *(unsigned*)&h; }
__device__ __forceinline__ __half2 u2h(unsigned u) { return *(__half2*)&u; }
__device__ __forceinline__ void mma_f16(float c[4], const unsigned a[4],
                                        unsigned b0, unsigned b1) {
    asm volatile(
        "mma.sync.aligned.m16n8k16.row.col.f32.f16.f16.f32 "
        "{%0,%1,%2,%3}, {%4,%5,%6,%7}, {%8,%9}, {%0,%1,%2,%3};"
        : "+f"(c[0]), "+f"(c[1]), "+f"(c[2]), "+f"(c[3])
        : "r"(a[0]), "r"(a[1]), "r"(a[2]), "r"(a[3]), "r"(b0), "r"(b1));
}
__device__ __forceinline__ uint32_t smem_u32(const void* p) {
    uint32_t a;
    asm("{ .reg .u64 t; cvta.to.shared.u64 t, %1; cvt.u32.u64 %0, t; }" : "=r"(a) : "l"(p));
    return a;
}
__device__ __forceinline__ void cp_async16(uint32_t dst, const void* src) {
    asm volatile("cp.async.cg.shared.global [%0], [%1], 16;" :: "r"(dst), "l"(src));
}
#define CP_COMMIT() asm volatile("cp.async.commit_group;" ::: "memory")
#define CP_WAIT0()  asm volatile("cp.async.wait_group 0;" ::: "memory")

// ---------------------------------------------------------------------------
// Merged conversion kernel: x + all 6 weights in ONE launch.
// Task layout (each task = one float4-pair -> uint4 or x float4 -> uint2):
//   [0, TX): x rows           TX = 8192*256
//   then Wq, Wk, Wv (512*256 each), Wi (512*16), W1 (544*512), W2 (1024*256)
// ---------------------------------------------------------------------------
#define TX   (MTOT * 256)
#define TWQ  (512 * 256)
#define TWI  (512 * 16)
#define TW1  (544 * 512)
#define TW2  (1024 * 256)
#define TTOT (TX + 3 * TWQ + TWI + TW1 + TW2)

__device__ __forceinline__ void conv_w_task(
    const float* __restrict__ W, __half2* __restrict__ Wh, int N, int t)
{
    int nq = N >> 2;
    int kp = t / nq, n4 = (t - kp * nq) << 2;
    float4 a = *(const float4*)(W + (size_t)(2 * kp) * N + n4);
    float4 b = *(const float4*)(W + (size_t)(2 * kp + 1) * N + n4);
    uint4 o;
    o.x = h2u(__floats2half2_rn(a.x, b.x));
    o.y = h2u(__floats2half2_rn(a.y, b.y));
    o.z = h2u(__floats2half2_rn(a.z, b.z));
    o.w = h2u(__floats2half2_rn(a.w, b.w));
    *(uint4*)(Wh + (size_t)kp * N + n4) = o;
}

__global__ __launch_bounds__(256) void conv_all(
    const float* __restrict__ x,
    const float* __restrict__ Wq, const float* __restrict__ Wk,
    const float* __restrict__ Wv, const float* __restrict__ Wi,
    const float* __restrict__ W1, const float* __restrict__ W2)
{
    int idx = blockIdx.x * 256 + threadIdx.x;
    if (idx < TX) {
        int row = idx >> 8, c4 = (idx & 255) << 2;
        float4 v = *(const float4*)(x + (size_t)row * DIM + c4);
        uint2 o;
        o.x = h2u(__floats2half2_rn(v.x, v.y));
        o.y = h2u(__floats2half2_rn(v.z, v.w));
        *(uint2*)((unsigned*)g_xh + (size_t)row * 512 + (c4 >> 1)) = o;
        return;
    }
    idx -= TX;
    if (idx < TWQ) { conv_w_task(Wq, g_whq, 1024, idx); return; }
    idx -= TWQ;
    if (idx < TWQ) { conv_w_task(Wk, g_whk, 1024, idx); return; }
    idx -= TWQ;
    if (idx < TWQ) { conv_w_task(Wv, g_whv, 1024, idx); return; }
    idx -= TWQ;
    if (idx < TWI) { conv_w_task(Wi, g_whi, 64, idx); return; }
    idx -= TWI;
    if (idx < TW1) { conv_w_task(W1, g_wh1, 2048, idx); return; }
    idx -= TW1;
    if (idx < TW2) { conv_w_task(W2, g_wh2, 1024, idx); return; }
}

// ---------------------------------------------------------------------------
// fp16 GEMM v5: all-half, BK=64. CTA 128x128, 256 thr = 8 warps (2M x 4N).
// A: half gmem rows -> raw cp.async, smem rows 32 data words pad to 36.
// B: packed half2 [kp][N] -> raw cp.async, rows of 136 words. Double buffered.
// ---------------------------------------------------------------------------
#define ASTR5 36
#define BSTR5 136
#define A5W (128 * ASTR5)     // 4608
#define B5W (32 * BSTR5)      // 4352
#define STG5 (A5W + B5W)      // 8960 words
#define SMEM5 (2 * STG5 * 4)  // 71680 B

template<bool OUTH, bool RELU>
__device__ __forceinline__ void gemm_core5(
    const __half2* __restrict__ Ah, int ldaw, int K, int m0,
    const __half2* __restrict__ Bh, int ldw, int n0w, int ncols,
    const float* __restrict__ bias, void* Cp, int ldCo, int c0o,
    unsigned* smw)
{
    const int tid = threadIdx.x, lane = tid & 31, warp = tid >> 5;
    const int wm = warp & 1, wn = warp >> 1;
    const int g = lane >> 2, tg = lane & 3;
    const uint32_t ss = smem_u32(smw);

    const int aoff[2] = {0, STG5};
    const int boff[2] = {A5W, STG5 + A5W};

    float acc[4][4][4];
#pragma unroll
    for (int mi = 0; mi < 4; mi++)
#pragma unroll
        for (int ni = 0; ni < 4; ni++)
#pragma unroll
            for (int r = 0; r < 4; r++) acc[mi][ni][r] = 0.f;

    const int NC = K >> 6;            // 64-k chunks (32 words)
    const int gpr = ncols >> 2;       // B granules per row
    const int ngr = 32 * gpr;         // granules per 32-row B chunk

    // --- prologue: chunk 0 ---
#pragma unroll
    for (int i = 0; i < 4; i++) {     // A: 1024 granules
        int gi = i * 256 + tid;
        int row = gi >> 3, c4 = (gi & 7) << 2;
        cp_async16(ss + (aoff[0] + row * ASTR5 + c4) * 4,
                   Ah + (size_t)(m0 + row) * ldaw + c4);
    }
    for (int gi = tid; gi < ngr; gi += 256) {
        int row = gi / gpr, n4 = (gi - row * gpr) << 2;
        cp_async16(ss + (boff[0] + row * BSTR5 + n4) * 4,
                   Bh + (size_t)row * ldw + n0w + n4);
    }
    CP_COMMIT();
    CP_WAIT0();
    __syncthreads();

    for (int ch = 0; ch < NC; ch++) {
        const int s = ch & 1;
        const bool more = (ch + 1 < NC);
        if (more) {
            const int k0w = (ch + 1) << 5;
#pragma unroll
            for (int i = 0; i < 4; i++) {
                int gi = i * 256 + tid;
                int row = gi >> 3, c4 = (gi & 7) << 2;
                cp_async16(ss + (aoff[s ^ 1] + row * ASTR5 + c4) * 4,
                           Ah + (size_t)(m0 + row) * ldaw + k0w + c4);
            }
            for (int gi = tid; gi < ngr; gi += 256) {
                int row = gi / gpr, n4 = (gi - row * gpr) << 2;
                cp_async16(ss + (boff[s ^ 1] + row * BSTR5 + n4) * 4,
                           Bh + (size_t)(k0w + row) * ldw + n0w + n4);
            }
            CP_COMMIT();
        }

        const unsigned* Aw = smw + aoff[s];
        const unsigned* Bw = smw + boff[s];
#pragma unroll
        for (int ks = 0; ks < 4; ks++) {
            unsigned a[4][4];
#pragma unroll
            for (int mi = 0; mi < 4; mi++) {
                const unsigned* ap = Aw + (wm * 64 + mi * 16 + g) * ASTR5 + ks * 8 + tg;
                a[mi][0] = ap[0];             a[mi][2] = ap[4];
                a[mi][1] = ap[8 * ASTR5];     a[mi][3] = ap[8 * ASTR5 + 4];
            }
#pragma unroll
            for (int ni = 0; ni < 4; ni++) {
                const unsigned* bp = Bw + (ks * 8 + tg) * BSTR5 + wn * 32 + ni * 8 + g;
                unsigned b0 = bp[0], b1 = bp[4 * BSTR5];
#pragma unroll
                for (int mi = 0; mi < 4; mi++)
                    mma_f16(acc[mi][ni], a[mi], b0, b1);
            }
        }

        if (more) CP_WAIT0();
        __syncthreads();
    }

    // ---- epilogue ----
    if (wn * 32 >= ncols) return;
#pragma unroll
    for (int mi = 0; mi < 4; mi++) {
        int r = m0 + wm * 64 + mi * 16 + g;
#pragma unroll
        for (int ni = 0; ni < 4; ni++) {
            int cl = wn * 32 + ni * 8 + 2 * tg;
            float b0 = bias[cl], b1 = bias[cl + 1];
            float v0 = acc[mi][ni][0] + b0, v1 = acc[mi][ni][1] + b1;
            float v2 = acc[mi][ni][2] + b0, v3 = acc[mi][ni][3] + b1;
            if (RELU) {
                v0 = fmaxf(v0, 0.f); v1 = fmaxf(v1, 0.f);
                v2 = fmaxf(v2, 0.f); v3 = fmaxf(v3, 0.f);
            }
            if (OUTH) {
                unsigned* Ch = (unsigned*)Cp;
                int w = c0o + wn * 16 + ni * 4 + tg;
                Ch[(size_t)r * ldCo + w]       = h2u(__floats2half2_rn(v0, v1));
                Ch[(size_t)(r + 8) * ldCo + w] = h2u(__floats2half2_rn(v2, v3));
            } else {
                float* Cf = (float*)Cp;
                *(float2*)(Cf + (size_t)r * ldCo + c0o + cl)       = make_float2(v0, v1);
                *(float2*)(Cf + (size_t)(r + 8) * ldCo + c0o + cl) = make_float2(v2, v3);
            }
        }
    }
}

__global__ __launch_bounds__(256, 2) void qkv_v5(
    const float* __restrict__ bq, const float* __restrict__ bk,
    const float* __restrict__ bv, const float* __restrict__ bi)
{
    extern __shared__ unsigned smw[];
    const int nt = blockIdx.x, m0 = blockIdx.y * 128;
    if (nt < 24) {
        const int seg = nt >> 3, tile = nt & 7;
        const __half2* W = (seg == 0) ? g_whq : (seg == 1) ? g_whk : g_whv;
        const float* bb  = (seg == 0) ? bq : (seg == 1) ? bk : bv;
        gemm_core5<true, false>(g_xh, 512, 1024, m0, W, 1024, tile * 128, 128,
                                bb + tile * 128, g_qkvh, 1536,
                                seg * 512 + tile * 64, smw);
    } else {
        gemm_core5<true, false>(g_xh, 512, 1024, m0, g_whi, 64, 0, 64,
                                bi, g_cath, 544, 512, smw);
    }
}

__global__ __launch_bounds__(256, 2) void ffn1_v5(const float* __restrict__ b1)
{
    extern __shared__ unsigned smw[];
    const int n0 = blockIdx.x * 128;
    gemm_core5<true, true>(g_cath, 544, 1088, blockIdx.y * 128, g_wh1, DFF, n0, 128,
                           b1 + n0, g_hh, 1024, n0 >> 1, smw);
}

__global__ __launch_bounds__(256, 2) void ffn2_v5(const float* __restrict__ b2,
                                                  float* __restrict__ out)
{
    extern __shared__ unsigned smw[];
    const int n0 = blockIdx.x * 128;
    gemm_core5<false, false>(g_hh, 1024, 2048, blockIdx.y * 128, g_wh2, DIM, n0, 128,
                             b2 + n0, out, DIM, n0, smw);
}

// ---------------------------------------------------------------------------
// fp16 flash attention. CTA 128 thr / 4 warps, 64 q rows, 32-key chunks.
// HD=64 -> 32 half2 words per row.
// ---------------------------------------------------------------------------
#define AQSTR 36
#define AVSTR 20
#define APSTR 20

__global__ __launch_bounds__(128) void attn_f16()
{
    __shared__ unsigned Qs[64 * AQSTR];
    __shared__ unsigned Ks[32 * AQSTR];
    __shared__ unsigned Vt[64 * AVSTR];
    __shared__ unsigned Ps[4 * 16 * APSTR];

    const int tid = threadIdx.x, lane = tid & 31, warp = tid >> 5;
    const int g = lane >> 2, tg = lane & 3;
    const int b = blockIdx.z, h = blockIdx.y, q0 = blockIdx.x * 64;

    const unsigned* qbase = (const unsigned*)g_qkvh + (size_t)(b * SEQ) * 1536 + h * 32;
    const unsigned* kbase = qbase + 512;
    const unsigned* vbase = qbase + 1024;

    // Q tile 64 rows x 32 words, scaled by 0.125
    {
        const __half2 qsc = __float2half2_rn(0.125f);
#pragma unroll
        for (int i = 0; i < 4; i++) {
            int idx = i * 128 + tid;
            int row = idx >> 3, c4 = (idx & 7) << 2;
            uint4 v = *(const uint4*)(qbase + (size_t)(q0 + row) * 1536 + c4);
            __half2* hp = (__half2*)&v;
            hp[0] = __hmul2(hp[0], qsc); hp[1] = __hmul2(hp[1], qsc);
            hp[2] = __hmul2(hp[2], qsc); hp[3] = __hmul2(hp[3], qsc);
            *(uint4*)(Qs + row * AQSTR + c4) = v;
        }
    }

    float rowm[2] = {-1e30f, -1e30f};
    float rowl[2] = {0.f, 0.f};
    float o[8][4];
#pragma unroll
    for (int nf = 0; nf < 8; nf++)
#pragma unroll
        for (int r = 0; r < 4; r++) o[nf][r] = 0.f;

    const int qrow0 = q0 + warp * 16 + g;
    unsigned* Pw = Ps + warp * 16 * APSTR;

    for (int c0 = 0; c0 < SEQ; c0 += 32) {
        __syncthreads();
        // K tile 32 rows x 32 words
#pragma unroll
        for (int i = 0; i < 2; i++) {
            int idx = i * 128 + tid;
            int row = idx >> 3, c4 = (idx & 7) << 2;
            *(uint4*)(Ks + row * AQSTR + c4) =
                *(const uint4*)(kbase + (size_t)(c0 + row) * 1536 + c4);
        }
        // V transpose to Vt[d][kp]
        {
            int wi = tid & 31, rb = tid >> 5;
#pragma unroll
            for (int rr = rb; rr < 16; rr += 4) {
                unsigned u0 = vbase[(size_t)(c0 + 2 * rr) * 1536 + wi];
                unsigned u1 = vbase[(size_t)(c0 + 2 * rr + 1) * 1536 + wi];
                __half2 va = u2h(u0), vb = u2h(u1);
                Vt[(2 * wi) * AVSTR + rr]     = h2u(__lows2half2(va, vb));
                Vt[(2 * wi + 1) * AVSTR + rr] = h2u(__highs2half2(va, vb));
            }
        }
        __syncthreads();

        // S (16x32 per warp) = Q · K^T, d=64 -> 4 ksteps
        float s[4][4];
#pragma unroll
        for (int ni = 0; ni < 4; ni++)
#pragma unroll
            for (int r = 0; r < 4; r++) s[ni][r] = 0.f;
#pragma unroll
        for (int ks = 0; ks < 4; ks++) {
            unsigned a[4];
            const unsigned* qp = Qs + (warp * 16 + g) * AQSTR + ks * 8 + tg;
            a[0] = qp[0];             a[2] = qp[4];
            a[1] = qp[8 * AQSTR];     a[3] = qp[8 * AQSTR + 4];
#pragma unroll
            for (int ni = 0; ni < 4; ni++) {
                const unsigned* kp = Ks + (ni * 8 + g) * AQSTR + ks * 8 + tg;
                mma_f16(s[ni], a, kp[0], kp[4]);
            }
        }

        // Diagonal mask + online softmax
        float cm0 = -1e30f, cm1 = -1e30f;
#pragma unroll
        for (int ni = 0; ni < 4; ni++) {
            int col = c0 + ni * 8 + 2 * tg;
            if (col     == qrow0)     s[ni][0] = -1e30f;
            if (col + 1 == qrow0)     s[ni][1] = -1e30f;
            if (col     == qrow0 + 8) s[ni][2] = -1e30f;
            if (col + 1 == qrow0 + 8) s[ni][3] = -1e30f;
            cm0 = fmaxf(cm0, fmaxf(s[ni][0], s[ni][1]));
            cm1 = fmaxf(cm1, fmaxf(s[ni][2], s[ni][3]));
        }
        cm0 = fmaxf(cm0, __shfl_xor_sync(0xffffffffu, cm0, 1));
        cm0 = fmaxf(cm0, __shfl_xor_sync(0xffffffffu, cm0, 2));
        cm1 = fmaxf(cm1, __shfl_xor_sync(0xffffffffu, cm1, 1));
        cm1 = fmaxf(cm1, __shfl_xor_sync(0xffffffffu, cm1, 2));

        float mn0 = fmaxf(rowm[0], cm0), mn1 = fmaxf(rowm[1], cm1);
        float sc0 = __expf(rowm[0] - mn0), sc1 = __expf(rowm[1] - mn1);
        rowm[0] = mn0; rowm[1] = mn1;
        rowl[0] *= sc0; rowl[1] *= sc1;
#pragma unroll
        for (int nf = 0; nf < 8; nf++) {
            o[nf][0] *= sc0; o[nf][1] *= sc0;
            o[nf][2] *= sc1; o[nf][3] *= sc1;
        }

        float ls0 = 0.f, ls1 = 0.f;
#pragma unroll
        for (int ni = 0; ni < 4; ni++) {
            float p0 = __expf(s[ni][0] - mn0), p1 = __expf(s[ni][1] - mn0);
            float p2 = __expf(s[ni][2] - mn1), p3 = __expf(s[ni][3] - mn1);
            ls0 += p0 + p1; ls1 += p2 + p3;
            Pw[g * APSTR + ni * 4 + tg]       = h2u(__floats2half2_rn(p0, p1));
            Pw[(g + 8) * APSTR + ni * 4 + tg] = h2u(__floats2half2_rn(p2, p3));
        }
        ls0 += __shfl_xor_sync(0xffffffffu, ls0, 1);
        ls0 += __shfl_xor_sync(0xffffffffu, ls0, 2);
        ls1 += __shfl_xor_sync(0xffffffffu, ls1, 1);
        ls1 += __shfl_xor_sync(0xffffffffu, ls1, 2);
        rowl[0] += ls0; rowl[1] += ls1;
        __syncwarp();

        // O += P(16x32) · V(32x64)
#pragma unroll
        for (int ks = 0; ks < 2; ks++) {
            unsigned a[4];
            a[0] = Pw[g * APSTR + ks * 8 + tg];
            a[1] = Pw[(g + 8) * APSTR + ks * 8 + tg];
            a[2] = Pw[g * APSTR + ks * 8 + tg + 4];
            a[3] = Pw[(g + 8) * APSTR + ks * 8 + tg + 4];
#pragma unroll
            for (int nf = 0; nf < 8; nf++) {
                const unsigned* vp = Vt + (nf * 8 + g) * AVSTR + ks * 8 + tg;
                mma_f16(o[nf], a, vp[0], vp[4]);
            }
        }
    }

    // Epilogue
    float inv0 = 1.f / rowl[0], inv1 = 1.f / rowl[1];
    unsigned* orow = (unsigned*)g_cath + (size_t)(b * SEQ + qrow0) * 544 + h * 32;
#pragma unroll
    for (int nf = 0; nf < 8; nf++) {
        int w = nf * 4 + tg;
        orow[w]           = h2u(__floats2half2_rn(o[nf][0] * inv0, o[nf][1] * inv0));
        orow[8 * 544 + w] = h2u(__floats2half2_rn(o[nf][2] * inv1, o[nf][3] * inv1));
    }
}

// ---------------------------------------------------------------------------
extern "C" void kernel_launch(void* const* d_in, const int* in_sizes, int n_in,
                              void* d_out, int out_size)
{
    const float* x   = (const float*)d_in[0];
    const float* Wq  = (const float*)d_in[1];
    const float* bq  = (const float*)d_in[2];
    const float* Wk  = (const float*)d_in[3];
    const float* bk  = (const float*)d_in[4];
    const float* Wv  = (const float*)d_in[5];
    const float* bv  = (const float*)d_in[6];
    const float* Wi  = (const float*)d_in[7];
    const float* bi  = (const float*)d_in[8];
    const float* W1  = (const float*)d_in[9];
    const float* b1  = (const float*)d_in[10];
    const float* W2  = (const float*)d_in[11];
    const float* b2  = (const float*)d_in[12];
    float* out = (float*)d_out;

    static bool configured = false;
    if (!configured) {
        cudaFuncSetAttribute(qkv_v5,  cudaFuncAttributeMaxDynamicSharedMemorySize, SMEM5);
        cudaFuncSetAttribute(ffn1_v5, cudaFuncAttributeMaxDynamicSharedMemorySize, SMEM5);
        cudaFuncSetAttribute(ffn2_v5, cudaFuncAttributeMaxDynamicSharedMemorySize, SMEM5);
        configured = true;
    }

    // 1: all conversions in one launch
    conv_all<<<(TTOT + 255) / 256, 256>>>(x, Wq, Wk, Wv, Wi, W1, W2);
    // 2: QKV + input projection
    qkv_v5<<<dim3(25, 64), 256, SMEM5>>>(bq, bk, bv, bi);
    // 3: Attention -> g_cath[:, 0:512w]
    attn_f16<<<dim3(SEQ / 64, NH, BSZ), 128>>>();
    // 4: FFN1 -> g_hh (relu)
    ffn1_v5<<<dim3(DFF / 128, MTOT / 128), 256, SMEM5>>>(b1);
    // 5: FFN2 -> out (fp32)  [this is launch #5 -> ncu capture target]
    ffn2_v5<<<dim3(DIM / 128, MTOT / 128), 256, SMEM5>>>(b2, out);
}

// round 11
// speedup vs baseline: 2.4265x; 1.0530x over previous
#include <cuda_runtime.h>
#include <cuda_fp16.h>
#include <math.h>
#include <stdint.h>

#define BSZ 8
#define SEQ 1024
#define DIM 1024
#define NH 16
#define HD 64
#define MTOT 8192
#define DCAT 1088
#define DFF 2048

// fp16 intermediates (__device__ globals per allocation-free rule), half2 words
__device__ __half2 g_xh[(size_t)MTOT * 512];      // x            [m, 512w]
__device__ __half2 g_qkvh[(size_t)MTOT * 1536];   // q | k | v    [m, 1536w]
__device__ __half2 g_cath[(size_t)MTOT * 544];    // attn|inproj  [m, 544w]
__device__ __half2 g_hh[(size_t)MTOT * 1024];     // ffn hidden   [m, 1024w]

// Pre-converted weights: word(kp, n) = half2(W[2kp][n], W[2kp+1][n])
__device__ __half2 g_whq[512 * 1024];
__device__ __half2 g_whk[512 * 1024];
__device__ __half2 g_whv[512 * 1024];
__device__ __half2 g_whi[512 * 64];
__device__ __half2 g_wh1[544 * 2048];
__device__ __half2 g_wh2[1024 * 1024];

__device__ __forceinline__ unsigned h2u(__half2 h) { return *(unsigned*)&h; }
__device__ __forceinline__ __half2 u2h(unsigned u) { return *(__half2*)&u; }
__device__ __forceinline__ void mma_f16(float c[4], const unsigned a[4],
                                        unsigned b0, unsigned b1) {
    asm volatile(
        "mma.sync.aligned.m16n8k16.row.col.f32.f16.f16.f32 "
        "{%0,%1,%2,%3}, {%4,%5,%6,%7}, {%8,%9}, {%0,%1,%2,%3};"
        : "+f"(c[0]), "+f"(c[1]), "+f"(c[2]), "+f"(c[3])
        : "r"(a[0]), "r"(a[1]), "r"(a[2]), "r"(a[3]), "r"(b0), "r"(b1));
}
__device__ __forceinline__ void ldsm4(unsigned a[4], uint32_t addr) {
    asm volatile("ldmatrix.sync.aligned.m8n8.x4.shared.b16 {%0,%1,%2,%3}, [%4];"
        : "=r"(a[0]), "=r"(a[1]), "=r"(a[2]), "=r"(a[3]) : "r"(addr));
}
__device__ __forceinline__ uint32_t smem_u32(const void* p) {
    uint32_t a;
    asm("{ .reg .u64 t; cvta.to.shared.u64 t, %1; cvt.u32.u64 %0, t; }" : "=r"(a) : "l"(p));
    return a;
}
__device__ __forceinline__ void cp_async16(uint32_t dst, const void* src) {
    asm volatile("cp.async.cg.shared.global [%0], [%1], 16;" :: "r"(dst), "l"(src));
}
#define CP_COMMIT() asm volatile("cp.async.commit_group;" ::: "memory")
#define CP_WAIT0()  asm volatile("cp.async.wait_group 0;" ::: "memory")

// ---------------------------------------------------------------------------
// Merged conversion kernel (one launch).
// ---------------------------------------------------------------------------
#define TX   (MTOT * 256)
#define TWQ  (512 * 256)
#define TWI  (512 * 16)
#define TW1  (544 * 512)
#define TW2  (1024 * 256)
#define TTOT (TX + 3 * TWQ + TWI + TW1 + TW2)

__device__ __forceinline__ void conv_w_task(
    const float* __restrict__ W, __half2* __restrict__ Wh, int N, int t)
{
    int nq = N >> 2;
    int kp = t / nq, n4 = (t - kp * nq) << 2;
    float4 a = *(const float4*)(W + (size_t)(2 * kp) * N + n4);
    float4 b = *(const float4*)(W + (size_t)(2 * kp + 1) * N + n4);
    uint4 o;
    o.x = h2u(__floats2half2_rn(a.x, b.x));
    o.y = h2u(__floats2half2_rn(a.y, b.y));
    o.z = h2u(__floats2half2_rn(a.z, b.z));
    o.w = h2u(__floats2half2_rn(a.w, b.w));
    *(uint4*)(Wh + (size_t)kp * N + n4) = o;
}

__global__ __launch_bounds__(256) void conv_all(
    const float* __restrict__ x,
    const float* __restrict__ Wq, const float* __restrict__ Wk,
    const float* __restrict__ Wv, const float* __restrict__ Wi,
    const float* __restrict__ W1, const float* __restrict__ W2)
{
    int idx = blockIdx.x * 256 + threadIdx.x;
    if (idx < TX) {
        int row = idx >> 8, c4 = (idx & 255) << 2;
        float4 v = *(const float4*)(x + (size_t)row * DIM + c4);
        uint2 o;
        o.x = h2u(__floats2half2_rn(v.x, v.y));
        o.y = h2u(__floats2half2_rn(v.z, v.w));
        *(uint2*)((unsigned*)g_xh + (size_t)row * 512 + (c4 >> 1)) = o;
        return;
    }
    idx -= TX;
    if (idx < TWQ) { conv_w_task(Wq, g_whq, 1024, idx); return; }
    idx -= TWQ;
    if (idx < TWQ) { conv_w_task(Wk, g_whk, 1024, idx); return; }
    idx -= TWQ;
    if (idx < TWQ) { conv_w_task(Wv, g_whv, 1024, idx); return; }
    idx -= TWQ;
    if (idx < TWI) { conv_w_task(Wi, g_whi, 64, idx); return; }
    idx -= TWI;
    if (idx < TW1) { conv_w_task(W1, g_wh1, 2048, idx); return; }
    idx -= TW1;
    if (idx < TW2) { conv_w_task(W2, g_wh2, 1024, idx); return; }
}

// ---------------------------------------------------------------------------
// fp16 GEMM v6: BK=64, ldmatrix A fragments. CTA 128x128, 8 warps (2M x 4N).
// ---------------------------------------------------------------------------
#define ASTR5 36
#define BSTR5 136
#define A5W (128 * ASTR5)     // 4608
#define B5W (32 * BSTR5)      // 4352
#define STG5 (A5W + B5W)      // 8960 words
#define SMEM5 (2 * STG5 * 4)  // 71680 B

template<bool OUTH, bool RELU>
__device__ __forceinline__ void gemm_core6(
    const __half2* __restrict__ Ah, int ldaw, int K, int m0,
    const __half2* __restrict__ Bh, int ldw, int n0w, int ncols,
    const float* __restrict__ bias, void* Cp, int ldCo, int c0o,
    unsigned* smw)
{
    const int tid = threadIdx.x, lane = tid & 31, warp = tid >> 5;
    const int wm = warp & 1, wn = warp >> 1;
    const int g = lane >> 2, tg = lane & 3;
    const uint32_t ss = smem_u32(smw);

    // per-lane ldmatrix address components (m8n8.x4: matrices m0k0,m8k0,m0k8,m8k8)
    const int lrow = lane & 7, sel = lane >> 3;
    const int arow_l = wm * 64 + ((sel & 1) << 3) + lrow;
    const int akoff_l = (sel >> 1) << 2;

    const int aoff[2] = {0, STG5};
    const int boff[2] = {A5W, STG5 + A5W};

    float acc[4][4][4];
#pragma unroll
    for (int mi = 0; mi < 4; mi++)
#pragma unroll
        for (int ni = 0; ni < 4; ni++)
#pragma unroll
            for (int r = 0; r < 4; r++) acc[mi][ni][r] = 0.f;

    const int NC = K >> 6;
    const int gpr = ncols >> 2;
    const int ngr = 32 * gpr;

    // --- prologue: chunk 0 ---
#pragma unroll
    for (int i = 0; i < 4; i++) {
        int gi = i * 256 + tid;
        int row = gi >> 3, c4 = (gi & 7) << 2;
        cp_async16(ss + (aoff[0] + row * ASTR5 + c4) * 4,
                   Ah + (size_t)(m0 + row) * ldaw + c4);
    }
    for (int gi = tid; gi < ngr; gi += 256) {
        int row = gi / gpr, n4 = (gi - row * gpr) << 2;
        cp_async16(ss + (boff[0] + row * BSTR5 + n4) * 4,
                   Bh + (size_t)row * ldw + n0w + n4);
    }
    CP_COMMIT();
    CP_WAIT0();
    __syncthreads();

    for (int ch = 0; ch < NC; ch++) {
        const int s = ch & 1;
        const bool more = (ch + 1 < NC);
        if (more) {
            const int k0w = (ch + 1) << 5;
#pragma unroll
            for (int i = 0; i < 4; i++) {
                int gi = i * 256 + tid;
                int row = gi >> 3, c4 = (gi & 7) << 2;
                cp_async16(ss + (aoff[s ^ 1] + row * ASTR5 + c4) * 4,
                           Ah + (size_t)(m0 + row) * ldaw + k0w + c4);
            }
            for (int gi = tid; gi < ngr; gi += 256) {
                int row = gi / gpr, n4 = (gi - row * gpr) << 2;
                cp_async16(ss + (boff[s ^ 1] + row * BSTR5 + n4) * 4,
                           Bh + (size_t)(k0w + row) * ldw + n0w + n4);
            }
            CP_COMMIT();
        }

        const unsigned* Bw = smw + boff[s];
        const uint32_t abase = ss + (aoff[s] + arow_l * ASTR5 + akoff_l) * 4;
#pragma unroll
        for (int ks = 0; ks < 4; ks++) {
            unsigned a[4][4];
#pragma unroll
            for (int mi = 0; mi < 4; mi++)
                ldsm4(a[mi], abase + (mi * 16 * ASTR5 + ks * 8) * 4);
#pragma unroll
            for (int ni = 0; ni < 4; ni++) {
                const unsigned* bp = Bw + (ks * 8 + tg) * BSTR5 + wn * 32 + ni * 8 + g;
                unsigned b0 = bp[0], b1 = bp[4 * BSTR5];
#pragma unroll
                for (int mi = 0; mi < 4; mi++)
                    mma_f16(acc[mi][ni], a[mi], b0, b1);
            }
        }

        if (more) CP_WAIT0();
        __syncthreads();
    }

    // ---- epilogue ----
    if (wn * 32 >= ncols) return;
#pragma unroll
    for (int mi = 0; mi < 4; mi++) {
        int r = m0 + wm * 64 + mi * 16 + g;
#pragma unroll
        for (int ni = 0; ni < 4; ni++) {
            int cl = wn * 32 + ni * 8 + 2 * tg;
            float b0 = bias[cl], b1 = bias[cl + 1];
            float v0 = acc[mi][ni][0] + b0, v1 = acc[mi][ni][1] + b1;
            float v2 = acc[mi][ni][2] + b0, v3 = acc[mi][ni][3] + b1;
            if (RELU) {
                v0 = fmaxf(v0, 0.f); v1 = fmaxf(v1, 0.f);
                v2 = fmaxf(v2, 0.f); v3 = fmaxf(v3, 0.f);
            }
            if (OUTH) {
                unsigned* Ch = (unsigned*)Cp;
                int w = c0o + wn * 16 + ni * 4 + tg;
                Ch[(size_t)r * ldCo + w]       = h2u(__floats2half2_rn(v0, v1));
                Ch[(size_t)(r + 8) * ldCo + w] = h2u(__floats2half2_rn(v2, v3));
            } else {
                float* Cf = (float*)Cp;
                *(float2*)(Cf + (size_t)r * ldCo + c0o + cl)       = make_float2(v0, v1);
                *(float2*)(Cf + (size_t)(r + 8) * ldCo + c0o + cl) = make_float2(v2, v3);
            }
        }
    }
}

__global__ __launch_bounds__(256, 2) void qkv_v6(
    const float* __restrict__ bq, const float* __restrict__ bk,
    const float* __restrict__ bv, const float* __restrict__ bi)
{
    extern __shared__ unsigned smw[];
    const int nt = blockIdx.x, m0 = blockIdx.y * 128;
    if (nt < 24) {
        const int seg = nt >> 3, tile = nt & 7;
        const __half2* W = (seg == 0) ? g_whq : (seg == 1) ? g_whk : g_whv;
        const float* bb  = (seg == 0) ? bq : (seg == 1) ? bk : bv;
        gemm_core6<true, false>(g_xh, 512, 1024, m0, W, 1024, tile * 128, 128,
                                bb + tile * 128, g_qkvh, 1536,
                                seg * 512 + tile * 64, smw);
    } else {
        gemm_core6<true, false>(g_xh, 512, 1024, m0, g_whi, 64, 0, 64,
                                bi, g_cath, 544, 512, smw);
    }
}

__global__ __launch_bounds__(256, 2) void ffn1_v6(const float* __restrict__ b1)
{
    extern __shared__ unsigned smw[];
    const int n0 = blockIdx.x * 128;
    gemm_core6<true, true>(g_cath, 544, 1088, blockIdx.y * 128, g_wh1, DFF, n0, 128,
                           b1 + n0, g_hh, 1024, n0 >> 1, smw);
}

__global__ __launch_bounds__(256, 2) void ffn2_v6(const float* __restrict__ b2,
                                                  float* __restrict__ out)
{
    extern __shared__ unsigned smw[];
    const int n0 = blockIdx.x * 128;
    gemm_core6<false, false>(g_hh, 1024, 2048, blockIdx.y * 128, g_wh2, DIM, n0, 128,
                             b2 + n0, out, DIM, n0, smw);
}

// ---------------------------------------------------------------------------
// fp16 flash attention v2: 256 thr / 8 warps, 128 q rows per CTA, 32-key chunks.
// K/V tiles shared by all 8 warps (halves K/V L2 traffic vs 64-q version).
// ---------------------------------------------------------------------------
#define AQSTR 36
#define AVSTR 20
#define APSTR 20

__global__ __launch_bounds__(256) void attn_f16()
{
    __shared__ unsigned Qs[128 * AQSTR];       // 18.4 KB
    __shared__ unsigned Ks[32 * AQSTR];        //  4.6 KB
    __shared__ unsigned Vt[64 * AVSTR];        //  5.1 KB
    __shared__ unsigned Ps[8 * 16 * APSTR];    // 10.2 KB

    const int tid = threadIdx.x, lane = tid & 31, warp = tid >> 5;
    const int g = lane >> 2, tg = lane & 3;
    const int b = blockIdx.z, h = blockIdx.y, q0 = blockIdx.x * 128;

    const unsigned* qbase = (const unsigned*)g_qkvh + (size_t)(b * SEQ) * 1536 + h * 32;
    const unsigned* kbase = qbase + 512;
    const unsigned* vbase = qbase + 1024;

    // Q tile 128 rows x 32 words, scaled by 0.125 (1024 uint4 / 256 thr = 4)
    {
        const __half2 qsc = __float2half2_rn(0.125f);
#pragma unroll
        for (int i = 0; i < 4; i++) {
            int idx = i * 256 + tid;
            int row = idx >> 3, c4 = (idx & 7) << 2;
            uint4 v = *(const uint4*)(qbase + (size_t)(q0 + row) * 1536 + c4);
            __half2* hp = (__half2*)&v;
            hp[0] = __hmul2(hp[0], qsc); hp[1] = __hmul2(hp[1], qsc);
            hp[2] = __hmul2(hp[2], qsc); hp[3] = __hmul2(hp[3], qsc);
            *(uint4*)(Qs + row * AQSTR + c4) = v;
        }
    }

    float rowm[2] = {-1e30f, -1e30f};
    float rowl[2] = {0.f, 0.f};
    float o[8][4];
#pragma unroll
    for (int nf = 0; nf < 8; nf++)
#pragma unroll
        for (int r = 0; r < 4; r++) o[nf][r] = 0.f;

    const int qrow0 = q0 + warp * 16 + g;
    unsigned* Pw = Ps + warp * 16 * APSTR;

    for (int c0 = 0; c0 < SEQ; c0 += 32) {
        __syncthreads();
        // K tile 32 rows x 32 words (256 uint4 / 256 thr = 1)
        {
            int row = tid >> 3, c4 = (tid & 7) << 2;
            *(uint4*)(Ks + row * AQSTR + c4) =
                *(const uint4*)(kbase + (size_t)(c0 + row) * 1536 + c4);
        }
        // V transpose to Vt[d][kp]
        {
            int wi = tid & 31, rb = tid >> 5;
#pragma unroll
            for (int rr = rb; rr < 16; rr += 8) {
                unsigned u0 = vbase[(size_t)(c0 + 2 * rr) * 1536 + wi];
                unsigned u1 = vbase[(size_t)(c0 + 2 * rr + 1) * 1536 + wi];
                __half2 va = u2h(u0), vb = u2h(u1);
                Vt[(2 * wi) * AVSTR + rr]     = h2u(__lows2half2(va, vb));
                Vt[(2 * wi + 1) * AVSTR + rr] = h2u(__highs2half2(va, vb));
            }
        }
        __syncthreads();

        // S (16x32 per warp) = Q · K^T, d=64 -> 4 ksteps
        float s[4][4];
#pragma unroll
        for (int ni = 0; ni < 4; ni++)
#pragma unroll
            for (int r = 0; r < 4; r++) s[ni][r] = 0.f;
#pragma unroll
        for (int ks = 0; ks < 4; ks++) {
            unsigned a[4];
            const unsigned* qp = Qs + (warp * 16 + g) * AQSTR + ks * 8 + tg;
            a[0] = qp[0];             a[2] = qp[4];
            a[1] = qp[8 * AQSTR];     a[3] = qp[8 * AQSTR + 4];
#pragma unroll
            for (int ni = 0; ni < 4; ni++) {
                const unsigned* kp = Ks + (ni * 8 + g) * AQSTR + ks * 8 + tg;
                mma_f16(s[ni], a, kp[0], kp[4]);
            }
        }

        // Diagonal mask + online softmax
        float cm0 = -1e30f, cm1 = -1e30f;
#pragma unroll
        for (int ni = 0; ni < 4; ni++) {
            int col = c0 + ni * 8 + 2 * tg;
            if (col     == qrow0)     s[ni][0] = -1e30f;
            if (col + 1 == qrow0)     s[ni][1] = -1e30f;
            if (col     == qrow0 + 8) s[ni][2] = -1e30f;
            if (col + 1 == qrow0 + 8) s[ni][3] = -1e30f;
            cm0 = fmaxf(cm0, fmaxf(s[ni][0], s[ni][1]));
            cm1 = fmaxf(cm1, fmaxf(s[ni][2], s[ni][3]));
        }
        cm0 = fmaxf(cm0, __shfl_xor_sync(0xffffffffu, cm0, 1));
        cm0 = fmaxf(cm0, __shfl_xor_sync(0xffffffffu, cm0, 2));
        cm1 = fmaxf(cm1, __shfl_xor_sync(0xffffffffu, cm1, 1));
        cm1 = fmaxf(cm1, __shfl_xor_sync(0xffffffffu, cm1, 2));

        float mn0 = fmaxf(rowm[0], cm0), mn1 = fmaxf(rowm[1], cm1);
        float sc0 = __expf(rowm[0] - mn0), sc1 = __expf(rowm[1] - mn1);
        rowm[0] = mn0; rowm[1] = mn1;
        rowl[0] *= sc0; rowl[1] *= sc1;
#pragma unroll
        for (int nf = 0; nf < 8; nf++) {
            o[nf][0] *= sc0; o[nf][1] *= sc0;
            o[nf][2] *= sc1; o[nf][3] *= sc1;
        }

        float ls0 = 0.f, ls1 = 0.f;
#pragma unroll
        for (int ni = 0; ni < 4; ni++) {
            float p0 = __expf(s[ni][0] - mn0), p1 = __expf(s[ni][1] - mn0);
            float p2 = __expf(s[ni][2] - mn1), p3 = __expf(s[ni][3] - mn1);
            ls0 += p0 + p1; ls1 += p2 + p3;
            Pw[g * APSTR + ni * 4 + tg]       = h2u(__floats2half2_rn(p0, p1));
            Pw[(g + 8) * APSTR + ni * 4 + tg] = h2u(__floats2half2_rn(p2, p3));
        }
        ls0 += __shfl_xor_sync(0xffffffffu, ls0, 1);
        ls0 += __shfl_xor_sync(0xffffffffu, ls0, 2);
        ls1 += __shfl_xor_sync(0xffffffffu, ls1, 1);
        ls1 += __shfl_xor_sync(0xffffffffu, ls1, 2);
        rowl[0] += ls0; rowl[1] += ls1;
        __syncwarp();

        // O += P(16x32) · V(32x64)
#pragma unroll
        for (int ks = 0; ks < 2; ks++) {
            unsigned a[4];
            a[0] = Pw[g * APSTR + ks * 8 + tg];
            a[1] = Pw[(g + 8) * APSTR + ks * 8 + tg];
            a[2] = Pw[g * APSTR + ks * 8 + tg + 4];
            a[3] = Pw[(g + 8) * APSTR + ks * 8 + tg + 4];
#pragma unroll
            for (int nf = 0; nf < 8; nf++) {
                const unsigned* vp = Vt + (nf * 8 + g) * AVSTR + ks * 8 + tg;
                mma_f16(o[nf], a, vp[0], vp[4]);
            }
        }
    }

    // Epilogue
    float inv0 = 1.f / rowl[0], inv1 = 1.f / rowl[1];
    unsigned* orow = (unsigned*)g_cath + (size_t)(b * SEQ + qrow0) * 544 + h * 32;
#pragma unroll
    for (int nf = 0; nf < 8; nf++) {
        int w = nf * 4 + tg;
        orow[w]           = h2u(__floats2half2_rn(o[nf][0] * inv0, o[nf][1] * inv0));
        orow[8 * 544 + w] = h2u(__floats2half2_rn(o[nf][2] * inv1, o[nf][3] * inv1));
    }
}

// ---------------------------------------------------------------------------
extern "C" void kernel_launch(void* const* d_in, const int* in_sizes, int n_in,
                              void* d_out, int out_size)
{
    const float* x   = (const float*)d_in[0];
    const float* Wq  = (const float*)d_in[1];
    const float* bq  = (const float*)d_in[2];
    const float* Wk  = (const float*)d_in[3];
    const float* bk  = (const float*)d_in[4];
    const float* Wv  = (const float*)d_in[5];
    const float* bv  = (const float*)d_in[6];
    const float* Wi  = (const float*)d_in[7];
    const float* bi  = (const float*)d_in[8];
    const float* W1  = (const float*)d_in[9];
    const float* b1  = (const float*)d_in[10];
    const float* W2  = (const float*)d_in[11];
    const float* b2  = (const float*)d_in[12];
    float* out = (float*)d_out;

    static bool configured = false;
    if (!configured) {
        cudaFuncSetAttribute(qkv_v6,  cudaFuncAttributeMaxDynamicSharedMemorySize, SMEM5);
        cudaFuncSetAttribute(ffn1_v6, cudaFuncAttributeMaxDynamicSharedMemorySize, SMEM5);
        cudaFuncSetAttribute(ffn2_v6, cudaFuncAttributeMaxDynamicSharedMemorySize, SMEM5);
        configured = true;
    }

    // 1: all conversions
    conv_all<<<(TTOT + 255) / 256, 256>>>(x, Wq, Wk, Wv, Wi, W1, W2);
    // 2: QKV + input projection
    qkv_v6<<<dim3(25, 64), 256, SMEM5>>>(bq, bk, bv, bi);
    // 3: Attention -> g_cath[:, 0:512w]
    attn_f16<<<dim3(SEQ / 128, NH, BSZ), 256>>>();
    // 4: FFN1 -> g_hh (relu)
    ffn1_v6<<<dim3(DFF / 128, MTOT / 128), 256, SMEM5>>>(b1);
    // 5: FFN2 -> out (fp32)   [ncu capture target]
    ffn2_v6<<<dim3(DIM / 128, MTOT / 128), 256, SMEM5>>>(b2, out);
}